// round 3
// baseline (speedup 1.0000x reference)
#include <cuda_runtime.h>
#include <cuda_bf16.h>
#include <float.h>
#include <math.h>

// Problem constants
#define BC   128      // clouds
#define PP   1024     // points per cloud
#define NPTS (BC*PP)  // 131072
#define KNN  4

// Scratch (device globals; no allocation allowed)
__device__ float g_f [NPTS * 128];   // concat feature buffer [N,128]: x1|x2|x3
__device__ float g_h1[NPTS * 264];
__device__ float g_h2[NPTS * 264];
__device__ int   g_knn[NPTS * KNN];

// ---------------------------------------------------------------------------
// squared norm with fixed 4-accumulator pattern (must match dot() pattern so
// that self-distance cancels exactly)
template<int D>
__device__ __forceinline__ float sqnorm(const float* v) {
    float a0 = 0.f, a1 = 0.f, a2 = 0.f, a3 = 0.f;
#pragma unroll
    for (int d = 0; d + 3 < D; d += 4) {
        a0 = fmaf(v[d],   v[d],   a0);
        a1 = fmaf(v[d+1], v[d+1], a1);
        a2 = fmaf(v[d+2], v[d+2], a2);
        a3 = fmaf(v[d+3], v[d+3], a3);
    }
#pragma unroll
    for (int d = (D/4)*4; d < D; d++) a0 = fmaf(v[d], v[d], a0);
    return (a0 + a1) + (a2 + a3);
}

// ---------------------------------------------------------------------------
// Brute-force kNN (k=4, self included). One thread per point, smem neighbor
// tiles of 128 points. Tie-break: strict < keeps lowest index first (matches
// jax.lax.top_k).
template<int D>
__global__ void knn_kernel(const float* __restrict__ feat, int stride,
                           int* __restrict__ knn) {
    const int NT = 128;
    __shared__ float s[NT * D];
    __shared__ float ssq[NT];

    int cloud = blockIdx.x / (PP / 256);
    int tile  = blockIdx.x % (PP / 256);
    int gi    = cloud * PP + tile * 256 + threadIdx.x;

    float f[D];
#pragma unroll
    for (int d = 0; d < D; d++) f[d] = feat[(long)gi * stride + d];
    float sqi = sqnorm<D>(f);

    float bd0 = FLT_MAX, bd1 = FLT_MAX, bd2 = FLT_MAX, bd3 = FLT_MAX;
    int   bi0 = 0, bi1 = 0, bi2 = 0, bi3 = 0;

    for (int j0 = 0; j0 < PP; j0 += NT) {
        __syncthreads();
        for (int idx = threadIdx.x; idx < NT * D; idx += 256) {
            int r = idx / D, c = idx % D;
            s[r * D + c] = feat[(long)(cloud * PP + j0 + r) * stride + c];
        }
        __syncthreads();
        if (threadIdx.x < NT) ssq[threadIdx.x] = sqnorm<D>(&s[threadIdx.x * D]);
        __syncthreads();

        for (int jj = 0; jj < NT; jj++) {
            const float* srow = &s[jj * D];
            float d0 = 0.f, d1 = 0.f, d2 = 0.f, d3 = 0.f;
#pragma unroll
            for (int q = 0; q + 3 < D; q += 4) {
                float4 v = *(const float4*)&srow[q];
                d0 = fmaf(f[q],   v.x, d0);
                d1 = fmaf(f[q+1], v.y, d1);
                d2 = fmaf(f[q+2], v.z, d2);
                d3 = fmaf(f[q+3], v.w, d3);
            }
#pragma unroll
            for (int q = (D/4)*4; q < D; q++) d0 = fmaf(f[q], srow[q], d0);
            float dot  = (d0 + d1) + (d2 + d3);
            float dist = (sqi + ssq[jj]) - 2.0f * dot;
            int   j    = cloud * PP + j0 + jj;
            if (dist < bd3) {
                if (dist < bd2) {
                    bd3 = bd2; bi3 = bi2;
                    if (dist < bd1) {
                        bd2 = bd1; bi2 = bi1;
                        if (dist < bd0) { bd1 = bd0; bi1 = bi0; bd0 = dist; bi0 = j; }
                        else            { bd1 = dist; bi1 = j; }
                    } else { bd2 = dist; bi2 = j; }
                } else { bd3 = dist; bi3 = j; }
            }
        }
    }
    knn[gi*4+0] = bi0; knn[gi*4+1] = bi1; knn[gi*4+2] = bi2; knn[gi*4+3] = bi3;
}

// ---------------------------------------------------------------------------
// Edge conv: for each point i, over its 4 neighbors j build e=[x_i, x_j-x_i],
// h = relu(e@W1+b1)@W2+b2, max-aggregate. One warp per point; weights in smem.
template<int D, int C>
__global__ void edge_conv_kernel(const float* __restrict__ feat, int fstride,
                                 const int* __restrict__ knn,
                                 const float* __restrict__ W1, const float* __restrict__ b1,
                                 const float* __restrict__ W2, const float* __restrict__ b2,
                                 float* __restrict__ out, int ostride) {
    constexpr int E = 2 * D;
    __shared__ float sW1[E * C];
    __shared__ float sW2[C * C];
    __shared__ float sb1[C], sb2[C];
    __shared__ float se[8][E];
    __shared__ float sh[8][C];

    int tid = threadIdx.x;
    for (int i = tid; i < E * C; i += 256) sW1[i] = W1[i];
    for (int i = tid; i < C * C; i += 256) sW2[i] = W2[i];
    if (tid < C) { sb1[tid] = b1[tid]; sb2[tid] = b2[tid]; }
    __syncthreads();

    int w = tid / 32, lane = tid % 32;
    int pt = blockIdx.x * 8 + w;

    for (int d = lane; d < D; d += 32) se[w][d] = feat[(long)pt * fstride + d];

    float acc[2] = { -FLT_MAX, -FLT_MAX };

#pragma unroll
    for (int k = 0; k < KNN; k++) {
        __syncwarp();
        int j = knn[pt * 4 + k];
        for (int d = lane; d < D; d += 32)
            se[w][D + d] = feat[(long)j * fstride + d] - se[w][d];
        __syncwarp();
        for (int cc = lane; cc < C; cc += 32) {
            float hv = sb1[cc];
#pragma unroll
            for (int t = 0; t < E; t++) hv = fmaf(se[w][t], sW1[t * C + cc], hv);
            sh[w][cc] = fmaxf(hv, 0.f);
        }
        __syncwarp();
        int ui = 0;
        for (int cc = lane; cc < C; cc += 32, ui++) {
            float ov = sb2[cc];
#pragma unroll
            for (int t = 0; t < C; t++) ov = fmaf(sh[w][t], sW2[t * C + cc], ov);
            acc[ui] = fmaxf(acc[ui], ov);
        }
    }
    int ui = 0;
    for (int cc = lane; cc < C; cc += 32, ui++)
        out[(long)pt * ostride + cc] = acc[ui];
}

// ---------------------------------------------------------------------------
// GEMM: out[N,M] = act(A[N,K] @ W[K,M] + bias). 64x64 tile, BK=8, 4x4 micro.
__global__ void gemm_bias_act(const float* __restrict__ A, const float* __restrict__ W,
                              const float* __restrict__ bias, float* __restrict__ out,
                              int N, int K, int M, int relu) {
    __shared__ float As[8][64];
    __shared__ float Bs[8][64];
    int tid = threadIdx.x;
    int tx = tid % 16, ty = tid / 16;
    int n0 = blockIdx.y * 64;
    int m0 = blockIdx.x * 64;

    float acc[4][4];
#pragma unroll
    for (int r = 0; r < 4; r++)
#pragma unroll
        for (int c = 0; c < 4; c++) acc[r][c] = 0.f;

    for (int k0 = 0; k0 < K; k0 += 8) {
#pragma unroll
        for (int l = 0; l < 2; l++) {
            int idx = tid + l * 256;           // 0..511
            int row = idx >> 3, kk = idx & 7;  // A: [row][kk]
            As[kk][row] = A[(long)(n0 + row) * K + k0 + kk];
        }
#pragma unroll
        for (int l = 0; l < 2; l++) {
            int idx = tid + l * 256;
            int kk = idx >> 6, col = idx & 63; // B: [kk][col]
            int gm = m0 + col;
            Bs[kk][col] = (gm < M) ? W[(long)(k0 + kk) * M + gm] : 0.f;
        }
        __syncthreads();
#pragma unroll
        for (int kk = 0; kk < 8; kk++) {
            float4 av = *(const float4*)&As[kk][ty * 4];
            float4 bv = *(const float4*)&Bs[kk][tx * 4];
            acc[0][0] = fmaf(av.x, bv.x, acc[0][0]); acc[0][1] = fmaf(av.x, bv.y, acc[0][1]);
            acc[0][2] = fmaf(av.x, bv.z, acc[0][2]); acc[0][3] = fmaf(av.x, bv.w, acc[0][3]);
            acc[1][0] = fmaf(av.y, bv.x, acc[1][0]); acc[1][1] = fmaf(av.y, bv.y, acc[1][1]);
            acc[1][2] = fmaf(av.y, bv.z, acc[1][2]); acc[1][3] = fmaf(av.y, bv.w, acc[1][3]);
            acc[2][0] = fmaf(av.z, bv.x, acc[2][0]); acc[2][1] = fmaf(av.z, bv.y, acc[2][1]);
            acc[2][2] = fmaf(av.z, bv.z, acc[2][2]); acc[2][3] = fmaf(av.z, bv.w, acc[2][3]);
            acc[3][0] = fmaf(av.w, bv.x, acc[3][0]); acc[3][1] = fmaf(av.w, bv.y, acc[3][1]);
            acc[3][2] = fmaf(av.w, bv.z, acc[3][2]); acc[3][3] = fmaf(av.w, bv.w, acc[3][3]);
        }
        __syncthreads();
    }

#pragma unroll
    for (int r = 0; r < 4; r++) {
        int row = n0 + ty * 4 + r;
#pragma unroll
        for (int c = 0; c < 4; c++) {
            int col = m0 + tx * 4 + c;
            if (col < M) {
                float v = acc[r][c] + bias[col];
                if (relu) v = fmaxf(v, 0.f);
                out[(long)row * M + col] = v;
            }
        }
    }
}

// ---------------------------------------------------------------------------
// Final 264->2 linear + log_softmax. One warp per point.
__global__ void final_kernel(const float* __restrict__ H, const float* __restrict__ W4,
                             const float* __restrict__ b4, float* __restrict__ out, int N) {
    int warp = (blockIdx.x * blockDim.x + threadIdx.x) / 32;
    int lane = threadIdx.x % 32;
    if (warp >= N) return;
    const float* h = H + (long)warp * 264;
    float s0 = 0.f, s1 = 0.f;
    for (int t = lane; t < 264; t += 32) {
        float hv = h[t];
        s0 = fmaf(hv, W4[t * 2 + 0], s0);
        s1 = fmaf(hv, W4[t * 2 + 1], s1);
    }
#pragma unroll
    for (int o = 16; o > 0; o >>= 1) {
        s0 += __shfl_xor_sync(0xFFFFFFFFu, s0, o);
        s1 += __shfl_xor_sync(0xFFFFFFFFu, s1, o);
    }
    if (lane == 0) {
        float o0 = s0 + b4[0], o1 = s1 + b4[1];
        float m = fmaxf(o0, o1);
        float lse = m + logf(expf(o0 - m) + expf(o1 - m));
        out[warp * 2 + 0] = o0 - lse;
        out[warp * 2 + 1] = o1 - lse;
    }
}

// ---------------------------------------------------------------------------
extern "C" void kernel_launch(void* const* d_in, const int* in_sizes, int n_in,
                              void* d_out, int out_size) {
    const float* x    = (const float*)d_in[0];
    // d_in[1] = batch (unused; groups are contiguous arange//P)
    const float* c1W1 = (const float*)d_in[2];
    const float* c1b1 = (const float*)d_in[3];
    const float* c1W2 = (const float*)d_in[4];
    const float* c1b2 = (const float*)d_in[5];
    const float* c2W1 = (const float*)d_in[6];
    const float* c2b1 = (const float*)d_in[7];
    const float* c2W2 = (const float*)d_in[8];
    const float* c2b2 = (const float*)d_in[9];
    const float* c3W1 = (const float*)d_in[10];
    const float* c3b1 = (const float*)d_in[11];
    const float* c3W2 = (const float*)d_in[12];
    const float* c3b2 = (const float*)d_in[13];
    const float* mW1  = (const float*)d_in[14];
    const float* mb1  = (const float*)d_in[15];
    const float* mW2  = (const float*)d_in[16];
    const float* mb2  = (const float*)d_in[17];
    const float* mW3  = (const float*)d_in[18];
    const float* mb3  = (const float*)d_in[19];
    const float* mW4  = (const float*)d_in[20];
    const float* mb4  = (const float*)d_in[21];
    float* out = (float*)d_out;

    float *f, *h1, *h2; int* knn;
    cudaGetSymbolAddress((void**)&f,   g_f);
    cudaGetSymbolAddress((void**)&h1,  g_h1);
    cudaGetSymbolAddress((void**)&h2,  g_h2);
    cudaGetSymbolAddress((void**)&knn, g_knn);

    const int knn_blocks  = BC * (PP / 256);   // 512
    const int conv_blocks = NPTS / 8;          // 16384

    // conv1: d=1 -> c=32
    knn_kernel<1><<<knn_blocks, 256>>>(x, 1, knn);
    edge_conv_kernel<1, 32><<<conv_blocks, 256>>>(x, 1, knn, c1W1, c1b1, c1W2, c1b2, f + 0, 128);
    // conv2: d=32 -> c=32
    knn_kernel<32><<<knn_blocks, 256>>>(f + 0, 128, knn);
    edge_conv_kernel<32, 32><<<conv_blocks, 256>>>(f + 0, 128, knn, c2W1, c2b1, c2W2, c2b2, f + 32, 128);
    // conv3: d=32 -> c=64
    knn_kernel<32><<<knn_blocks, 256>>>(f + 32, 128, knn);
    edge_conv_kernel<32, 64><<<conv_blocks, 256>>>(f + 32, 128, knn, c3W1, c3b1, c3W2, c3b2, f + 64, 128);

    // final MLP on concat features f[N,128]
    dim3 g1((264 + 63) / 64, NPTS / 64);
    gemm_bias_act<<<g1, 256>>>(f,  mW1, mb1, h1, NPTS, 128, 264, 1);
    gemm_bias_act<<<g1, 256>>>(h1, mW2, mb2, h2, NPTS, 264, 264, 1);
    gemm_bias_act<<<g1, 256>>>(h2, mW3, mb3, h1, NPTS, 264, 264, 1);
    final_kernel<<<NPTS / 8, 256>>>(h1, mW4, mb4, out, NPTS);
}

// round 5
// speedup vs baseline: 1.0132x; 1.0132x over previous
#include <cuda_runtime.h>
#include <cuda_bf16.h>
#include <float.h>
#include <math.h>

// Problem constants
#define BC   128      // clouds
#define PP   1024     // points per cloud
#define NPTS (BC*PP)  // 131072
#define KNN  4

typedef unsigned long long ull;

// Scratch (device globals; no allocation allowed)
__device__ float g_f [NPTS * 128];   // concat feature buffer [N,128]: x1|x2|x3
__device__ float g_h1[NPTS * 264];
__device__ float g_h2[NPTS * 264];
__device__ int   g_knn[NPTS * KNN];

// ---------------------------------------------------------------------------
// packed f32x2 helpers (FFMA2 pipe — 2x fp32 FMA throughput on sm_103a)
__device__ __forceinline__ ull fma2(ull a, ull b, ull c) {
    ull d; asm("fma.rn.f32x2 %0, %1, %2, %3;" : "=l"(d) : "l"(a), "l"(b), "l"(c));
    return d;
}
__device__ __forceinline__ ull dup2(float x) {
    ull d; unsigned u = __float_as_uint(x);
    asm("mov.b64 %0, {%1, %1};" : "=l"(d) : "r"(u));
    return d;
}
__device__ __forceinline__ ull pack2(float lo, float hi) {
    ull d;
    asm("mov.b64 %0, {%1, %2};" : "=l"(d)
        : "r"(__float_as_uint(lo)), "r"(__float_as_uint(hi)));
    return d;
}
__device__ __forceinline__ float2 unpack2(ull v) {
    unsigned l, h;
    asm("mov.b64 {%0, %1}, %2;" : "=r"(l), "=r"(h) : "l"(v));
    return make_float2(__uint_as_float(l), __uint_as_float(h));
}

// 32-dim dot product on packed pairs (fixed accumulation pattern)
__device__ __forceinline__ float dot32p(const ull* a, const ull* b) {
    ull s0 = 0, s1 = 0;
#pragma unroll
    for (int q = 0; q < 16; q += 2) {
        s0 = fma2(a[q],   b[q],   s0);
        s1 = fma2(a[q+1], b[q+1], s1);
    }
    float2 x = unpack2(s0), y = unpack2(s1);
    return (x.x + x.y) + (y.x + y.y);
}

// ---------------------------------------------------------------------------
// generic-D squared norm (used by D=1 knn)
template<int D>
__device__ __forceinline__ float sqnorm(const float* v) {
    float a0 = 0.f;
#pragma unroll
    for (int d = 0; d < D; d++) a0 = fmaf(v[d], v[d], a0);
    return a0;
}

// ---------------------------------------------------------------------------
// Brute-force kNN for D=1 (conv1 input). One thread per point.
__global__ void knn1_kernel(const float* __restrict__ feat, int* __restrict__ kn) {
    const int NT = 256;
    __shared__ float s[NT];
    int cloud = blockIdx.x / (PP / 256);
    int tile  = blockIdx.x % (PP / 256);
    int gi    = cloud * PP + tile * 256 + threadIdx.x;

    float f0 = feat[gi];
    float bd0 = FLT_MAX, bd1 = FLT_MAX, bd2 = FLT_MAX, bd3 = FLT_MAX;
    int   bi0 = 0, bi1 = 0, bi2 = 0, bi3 = 0;

    for (int j0 = 0; j0 < PP; j0 += NT) {
        __syncthreads();
        s[threadIdx.x] = feat[cloud * PP + j0 + threadIdx.x];
        __syncthreads();
        for (int jj = 0; jj < NT; jj++) {
            float df = f0 - s[jj];
            float dist = df * df;
            int j = cloud * PP + j0 + jj;
            if (dist < bd3) {
                if (dist < bd2) {
                    bd3 = bd2; bi3 = bi2;
                    if (dist < bd1) {
                        bd2 = bd1; bi2 = bi1;
                        if (dist < bd0) { bd1 = bd0; bi1 = bi0; bd0 = dist; bi0 = j; }
                        else            { bd1 = dist; bi1 = j; }
                    } else { bd2 = dist; bi2 = j; }
                } else { bd3 = dist; bi3 = j; }
            }
        }
    }
    kn[gi*4+0] = bi0; kn[gi*4+1] = bi1; kn[gi*4+2] = bi2; kn[gi*4+3] = bi3;
}

// ---------------------------------------------------------------------------
// Brute-force kNN for D=32, packed f32x2 dot products. Thread per point.
__global__ void knn32_kernel(const float* __restrict__ feat, int stride,
                             int* __restrict__ kn) {
    const int NT = 128;
    __shared__ float s[NT * 32];
    __shared__ float ssq[NT];

    int tid   = threadIdx.x;
    int cloud = blockIdx.x >> 2;
    int tile  = blockIdx.x & 3;
    int gi    = cloud * PP + tile * 256 + tid;

    ull fp[16];
    const float* fi = feat + (long)gi * stride;
#pragma unroll
    for (int q = 0; q < 8; q++) {
        float4 v = *(const float4*)(fi + q * 4);
        fp[2*q]   = pack2(v.x, v.y);
        fp[2*q+1] = pack2(v.z, v.w);
    }
    float sqi = dot32p(fp, fp);

    float bd0 = FLT_MAX, bd1 = FLT_MAX, bd2 = FLT_MAX, bd3 = FLT_MAX;
    int   bi0 = 0, bi1 = 0, bi2 = 0, bi3 = 0;

    for (int j0 = 0; j0 < PP; j0 += NT) {
        __syncthreads();
#pragma unroll
        for (int l = 0; l < 4; l++) {
            int idx = tid + l * 256;           // 0..1023 float4 slots
            int row = idx >> 3, c4 = idx & 7;
            *(float4*)&s[row * 32 + c4 * 4] =
                *(const float4*)(feat + (long)(cloud * PP + j0 + row) * stride + c4 * 4);
        }
        __syncthreads();
        if (tid < NT) {
            const ull* sp = (const ull*)&s[tid * 32];
            ull t[16];
#pragma unroll
            for (int q = 0; q < 16; q++) t[q] = sp[q];
            ssq[tid] = dot32p(t, t);
        }
        __syncthreads();

        for (int jj = 0; jj < NT; jj++) {
            const ull* sp = (const ull*)&s[jj * 32];
            ull s0 = 0, s1 = 0;
#pragma unroll
            for (int q = 0; q < 16; q += 2) {
                s0 = fma2(fp[q],   sp[q],   s0);
                s1 = fma2(fp[q+1], sp[q+1], s1);
            }
            float2 x = unpack2(s0), y = unpack2(s1);
            float dot  = (x.x + x.y) + (y.x + y.y);
            float dist = (sqi + ssq[jj]) - 2.0f * dot;
            int   j    = cloud * PP + j0 + jj;
            if (dist < bd3) {
                if (dist < bd2) {
                    bd3 = bd2; bi3 = bi2;
                    if (dist < bd1) {
                        bd2 = bd1; bi2 = bi1;
                        if (dist < bd0) { bd1 = bd0; bi1 = bi0; bd0 = dist; bi0 = j; }
                        else            { bd1 = dist; bi1 = j; }
                    } else { bd2 = dist; bi2 = j; }
                } else { bd3 = dist; bi3 = j; }
            }
        }
    }
    kn[gi*4+0] = bi0; kn[gi*4+1] = bi1; kn[gi*4+2] = bi2; kn[gi*4+3] = bi3;
}

// ---------------------------------------------------------------------------
// Edge conv for D=1 (conv1): warp-per-point version (work is tiny).
__global__ void edge_conv1_kernel(const float* __restrict__ feat,
                                  const int* __restrict__ kn,
                                  const float* __restrict__ W1, const float* __restrict__ b1,
                                  const float* __restrict__ W2, const float* __restrict__ b2,
                                  float* __restrict__ out, int ostride) {
    const int C = 32;
    __shared__ float sW1[2 * C];
    __shared__ float sW2[C * C];
    __shared__ float sb1[C], sb2[C];
    __shared__ float sh[8][C];

    int tid = threadIdx.x;
    for (int i = tid; i < 2 * C; i += 256) sW1[i] = W1[i];
    for (int i = tid; i < C * C; i += 256) sW2[i] = W2[i];
    if (tid < C) { sb1[tid] = b1[tid]; sb2[tid] = b2[tid]; }
    __syncthreads();

    int w = tid / 32, lane = tid % 32;
    int pt = blockIdx.x * 8 + w;
    float xi = feat[pt];

    float acc = -FLT_MAX;
#pragma unroll
    for (int k = 0; k < KNN; k++) {
        int j = kn[pt * 4 + k];
        float dj = feat[j] - xi;
        // layer1: hv = relu(xi*W1[0][cc] + dj*W1[1][cc] + b1[cc])
        float hv = fmaf(xi, sW1[lane], fmaf(dj, sW1[C + lane], sb1[lane]));
        sh[w][lane] = fmaxf(hv, 0.f);
        __syncwarp();
        float ov = sb2[lane];
#pragma unroll
        for (int t = 0; t < C; t++) ov = fmaf(sh[w][t], sW2[t * C + lane], ov);
        acc = fmaxf(acc, ov);
        __syncwarp();
    }
    out[(long)pt * ostride + lane] = acc;
}

// ---------------------------------------------------------------------------
// Edge conv for D=32: thread-per-point (S=1) or 2 threads/point (S=2 output
// split, layer1 duplicated). Packed FFMA2 throughout; W1 transposed in smem
// so every weight load is a uniform broadcast.
template<int C, int S>
__global__ void __launch_bounds__(128)
edge_conv32(const float* __restrict__ feat, int fstride,
            const int* __restrict__ kn,
            const float* __restrict__ W1, const float* __restrict__ b1,
            const float* __restrict__ W2, const float* __restrict__ b2,
            float* __restrict__ out, int ostride) {
    constexpr int E  = 64;
    constexpr int CO = C / S;
    __shared__ float sW1T[C][E];    // sW1T[t2][t] = W1[t][t2]
    __shared__ float sW2[C][C];
    __shared__ float sb1[C];

    int tid = threadIdx.x;
    for (int i = tid; i < E * C; i += 128) sW1T[i % C][i / C] = W1[i];
    for (int i = tid; i < C * C; i += 128) sW2[i / C][i % C] = W2[i];
    for (int i = tid; i < C;     i += 128) sb1[i] = b1[i];
    __syncthreads();

    int thr = blockIdx.x * 128 + tid;
    int pt  = thr / S;
    int off = (thr % S) * CO;

    const float* xi_ptr = feat + (long)pt * fstride;
    ull xip[16];
#pragma unroll
    for (int q = 0; q < 8; q++) {
        float4 v = *(const float4*)(xi_ptr + q * 4);
        xip[2*q]   = pack2(v.x, v.y);
        xip[2*q+1] = pack2(v.z, v.w);
    }
    ull m1 = dup2(-1.0f);

    float omax[CO];
#pragma unroll
    for (int c = 0; c < CO; c++) omax[c] = -FLT_MAX;

#pragma unroll
    for (int k = 0; k < KNN; k++) {
        int j = kn[pt * 4 + k];
        const float* xj_ptr = feat + (long)j * fstride;
        ull dfp[16];
#pragma unroll
        for (int q = 0; q < 8; q++) {
            float4 v = *(const float4*)(xj_ptr + q * 4);
            dfp[2*q]   = fma2(xip[2*q],   m1, pack2(v.x, v.y));  // xj - xi
            dfp[2*q+1] = fma2(xip[2*q+1], m1, pack2(v.z, v.w));
        }
        ull oe[CO / 2];
#pragma unroll
        for (int c = 0; c < CO / 2; c++) oe[c] = 0;

        for (int t2 = 0; t2 < C; t2++) {
            const ull* wp = (const ull*)&sW1T[t2][0];   // broadcast reads
            ull h0 = 0, h1 = 0;
#pragma unroll
            for (int q = 0; q < 16; q += 2) {
                h0 = fma2(xip[q],   wp[q],   h0);
                h1 = fma2(xip[q+1], wp[q+1], h1);
            }
#pragma unroll
            for (int q = 0; q < 16; q += 2) {
                h0 = fma2(dfp[q],   wp[16 + q],   h0);
                h1 = fma2(dfp[q+1], wp[16 + q+1], h1);
            }
            float2 a = unpack2(h0), b = unpack2(h1);
            float hv = sb1[t2] + ((a.x + a.y) + (b.x + b.y));
            hv = fmaxf(hv, 0.0f);
            ull hv2 = dup2(hv);
            const ull* w2p = (const ull*)&sW2[t2][off];
#pragma unroll
            for (int c = 0; c < CO / 2; c++) oe[c] = fma2(hv2, w2p[c], oe[c]);
        }
#pragma unroll
        for (int c = 0; c < CO / 2; c++) {
            float2 p = unpack2(oe[c]);
            omax[2*c]   = fmaxf(omax[2*c],   p.x);
            omax[2*c+1] = fmaxf(omax[2*c+1], p.y);
        }
    }
#pragma unroll
    for (int c = 0; c < CO; c++)
        out[(long)pt * ostride + off + c] = omax[c] + b2[off + c];
}

// ---------------------------------------------------------------------------
// GEMM: out[N,M] = act(A[N,K] @ W[K,M] + bias). 128x64 tile, BK=16,
// 4x8 microtile held as packed f32x2 accumulators.
__global__ void __launch_bounds__(256)
gemm_f32x2(const float* __restrict__ A, const float* __restrict__ W,
           const float* __restrict__ bias, float* __restrict__ out,
           int N, int K, int M, int relu) {
    __shared__ float As[16][128];
    __shared__ float Bs[16][64];
    int tid = threadIdx.x;
    int tx = tid & 7, ty = tid >> 3;      // 8 col-groups x 32 row-groups
    int n0 = blockIdx.y * 128;
    int m0 = blockIdx.x * 64;

    ull acc[4][4];
#pragma unroll
    for (int r = 0; r < 4; r++)
#pragma unroll
        for (int c = 0; c < 4; c++) acc[r][c] = 0;

    int ktiles = (K + 15) >> 4;
    for (int kt = 0; kt < ktiles; kt++) {
        int k0 = kt << 4;
        // A tile -> transposed smem As[k][row]
#pragma unroll
        for (int l = 0; l < 2; l++) {
            int idx = tid + l * 256;                 // 512 float4 slots
            int row = idx & 127, kc = idx >> 7;      // kc 0..3
            float4 v = make_float4(0.f, 0.f, 0.f, 0.f);
            if (k0 + kc * 4 < K)
                v = *(const float4*)(A + (long)(n0 + row) * K + k0 + kc * 4);
            As[kc*4+0][row] = v.x; As[kc*4+1][row] = v.y;
            As[kc*4+2][row] = v.z; As[kc*4+3][row] = v.w;
        }
        // B tile
        {
            int kk = tid >> 4, cg = tid & 15;
            float4 v = make_float4(0.f, 0.f, 0.f, 0.f);
            int gm = m0 + cg * 4;
            if (k0 + kk < K && gm < M)
                v = *(const float4*)(W + (long)(k0 + kk) * M + gm);
            *(float4*)&Bs[kk][cg * 4] = v;
        }
        __syncthreads();
#pragma unroll
        for (int kk = 0; kk < 16; kk++) {
            float4 av = *(const float4*)&As[kk][ty * 4];
            ull a0 = dup2(av.x), a1 = dup2(av.y), a2 = dup2(av.z), a3 = dup2(av.w);
            ulonglong2 b01 = *(const ulonglong2*)&Bs[kk][tx * 8];
            ulonglong2 b23 = *(const ulonglong2*)&Bs[kk][tx * 8 + 4];
            acc[0][0] = fma2(a0, b01.x, acc[0][0]); acc[0][1] = fma2(a0, b01.y, acc[0][1]);
            acc[0][2] = fma2(a0, b23.x, acc[0][2]); acc[0][3] = fma2(a0, b23.y, acc[0][3]);
            acc[1][0] = fma2(a1, b01.x, acc[1][0]); acc[1][1] = fma2(a1, b01.y, acc[1][1]);
            acc[1][2] = fma2(a1, b23.x, acc[1][2]); acc[1][3] = fma2(a1, b23.y, acc[1][3]);
            acc[2][0] = fma2(a2, b01.x, acc[2][0]); acc[2][1] = fma2(a2, b01.y, acc[2][1]);
            acc[2][2] = fma2(a2, b23.x, acc[2][2]); acc[2][3] = fma2(a2, b23.y, acc[2][3]);
            acc[3][0] = fma2(a3, b01.x, acc[3][0]); acc[3][1] = fma2(a3, b01.y, acc[3][1]);
            acc[3][2] = fma2(a3, b23.x, acc[3][2]); acc[3][3] = fma2(a3, b23.y, acc[3][3]);
        }
        __syncthreads();
    }

#pragma unroll
    for (int r = 0; r < 4; r++) {
        int row = n0 + ty * 4 + r;
#pragma unroll
        for (int c = 0; c < 4; c++) {
            int col = m0 + tx * 8 + 2 * c;
            if (col < M) {
                float2 p = unpack2(acc[r][c]);
                float v0 = p.x + bias[col];
                float v1 = p.y + bias[col + 1];
                if (relu) { v0 = fmaxf(v0, 0.f); v1 = fmaxf(v1, 0.f); }
                *(float2*)(out + (long)row * M + col) = make_float2(v0, v1);
            }
        }
    }
}

// ---------------------------------------------------------------------------
// Final 264->2 linear + log_softmax. One warp per point.
__global__ void final_kernel(const float* __restrict__ H, const float* __restrict__ W4,
                             const float* __restrict__ b4, float* __restrict__ out, int N) {
    int warp = (blockIdx.x * blockDim.x + threadIdx.x) / 32;
    int lane = threadIdx.x % 32;
    if (warp >= N) return;
    const float* h = H + (long)warp * 264;
    float s0 = 0.f, s1 = 0.f;
    for (int t = lane; t < 264; t += 32) {
        float hv = h[t];
        s0 = fmaf(hv, W4[t * 2 + 0], s0);
        s1 = fmaf(hv, W4[t * 2 + 1], s1);
    }
#pragma unroll
    for (int o = 16; o > 0; o >>= 1) {
        s0 += __shfl_xor_sync(0xFFFFFFFFu, s0, o);
        s1 += __shfl_xor_sync(0xFFFFFFFFu, s1, o);
    }
    if (lane == 0) {
        float o0 = s0 + b4[0], o1 = s1 + b4[1];
        float m = fmaxf(o0, o1);
        float lse = m + logf(expf(o0 - m) + expf(o1 - m));
        out[warp * 2 + 0] = o0 - lse;
        out[warp * 2 + 1] = o1 - lse;
    }
}

// ---------------------------------------------------------------------------
extern "C" void kernel_launch(void* const* d_in, const int* in_sizes, int n_in,
                              void* d_out, int out_size) {
    const float* x    = (const float*)d_in[0];
    const float* c1W1 = (const float*)d_in[2];
    const float* c1b1 = (const float*)d_in[3];
    const float* c1W2 = (const float*)d_in[4];
    const float* c1b2 = (const float*)d_in[5];
    const float* c2W1 = (const float*)d_in[6];
    const float* c2b1 = (const float*)d_in[7];
    const float* c2W2 = (const float*)d_in[8];
    const float* c2b2 = (const float*)d_in[9];
    const float* c3W1 = (const float*)d_in[10];
    const float* c3b1 = (const float*)d_in[11];
    const float* c3W2 = (const float*)d_in[12];
    const float* c3b2 = (const float*)d_in[13];
    const float* mW1  = (const float*)d_in[14];
    const float* mb1  = (const float*)d_in[15];
    const float* mW2  = (const float*)d_in[16];
    const float* mb2  = (const float*)d_in[17];
    const float* mW3  = (const float*)d_in[18];
    const float* mb3  = (const float*)d_in[19];
    const float* mW4  = (const float*)d_in[20];
    const float* mb4  = (const float*)d_in[21];
    float* out = (float*)d_out;

    float *f, *h1, *h2; int* knn;
    cudaGetSymbolAddress((void**)&f,   g_f);
    cudaGetSymbolAddress((void**)&h1,  g_h1);
    cudaGetSymbolAddress((void**)&h2,  g_h2);
    cudaGetSymbolAddress((void**)&knn, g_knn);

    const int knn_blocks = BC * (PP / 256);   // 512

    // conv1: d=1 -> c=32
    knn1_kernel<<<knn_blocks, 256>>>(x, knn);
    edge_conv1_kernel<<<NPTS / 8, 256>>>(x, knn, c1W1, c1b1, c1W2, c1b2, f + 0, 128);
    // conv2: d=32 -> c=32 (thread per point)
    knn32_kernel<<<knn_blocks, 256>>>(f + 0, 128, knn);
    edge_conv32<32, 1><<<NPTS / 128, 128>>>(f + 0, 128, knn, c2W1, c2b1, c2W2, c2b2, f + 32, 128);
    // conv3: d=32 -> c=64 (2 threads per point, output split)
    knn32_kernel<<<knn_blocks, 256>>>(f + 32, 128, knn);
    edge_conv32<64, 2><<<2 * NPTS / 128, 128>>>(f + 32, 128, knn, c3W1, c3b1, c3W2, c3b2, f + 64, 128);

    // final MLP on concat features f[N,128]
    dim3 g1((264 + 63) / 64, NPTS / 128);
    gemm_f32x2<<<g1, 256>>>(f,  mW1, mb1, h1, NPTS, 128, 264, 1);
    gemm_f32x2<<<g1, 256>>>(h1, mW2, mb2, h2, NPTS, 264, 264, 1);
    gemm_f32x2<<<g1, 256>>>(h2, mW3, mb3, h1, NPTS, 264, 264, 1);
    final_kernel<<<NPTS / 8, 256>>>(h1, mW4, mb4, out, NPTS);
}

// round 7
// speedup vs baseline: 1.4728x; 1.4536x over previous
#include <cuda_runtime.h>
#include <cuda_bf16.h>
#include <float.h>
#include <math.h>
#include <stdint.h>

// Problem constants
#define BC   128
#define PP   1024
#define NPTS (BC*PP)   // 131072
#define KNN  4
#define KP3  288       // K padded to 288 (9 chunks of 32); N padded to 272
#define NP2  272

typedef unsigned long long ull;

// ---------------------------------------------------------------------------
// Scratch (device globals; no allocation allowed)
__device__ float          g_f   [NPTS * 64];        // fp32 [x1|x2] for kNN (stride 64)
__device__ __nv_bfloat16  g_fa_h[NPTS * 128];       // bf16-hi of concat feats (GEMM1 A)
__device__ __nv_bfloat16  g_fa_l[NPTS * 128];       // bf16-lo
__device__ __nv_bfloat16  g_xa_h[NPTS * KP3];       // h1 hi (GEMM2 A)
__device__ __nv_bfloat16  g_xa_l[NPTS * KP3];
__device__ __nv_bfloat16  g_ya_h[NPTS * KP3];       // h2 hi (GEMM3 A)
__device__ __nv_bfloat16  g_ya_l[NPTS * KP3];
__device__ float          g_h3  [NPTS * KP3];       // h3 fp32 for final layer
__device__ __nv_bfloat16  g_w_h [3][NP2 * KP3];     // transposed split weights [n][k]
__device__ __nv_bfloat16  g_w_l [3][NP2 * KP3];
__device__ int            g_knn [NPTS * KNN];

// ---------------------------------------------------------------------------
// packed f32x2 helpers (for SIMT kernels)
__device__ __forceinline__ ull fma2(ull a, ull b, ull c) {
    ull d; asm("fma.rn.f32x2 %0, %1, %2, %3;" : "=l"(d) : "l"(a), "l"(b), "l"(c));
    return d;
}
__device__ __forceinline__ ull dup2(float x) {
    ull d; unsigned u = __float_as_uint(x);
    asm("mov.b64 %0, {%1, %1};" : "=l"(d) : "r"(u));
    return d;
}
__device__ __forceinline__ ull pack2(float lo, float hi) {
    ull d;
    asm("mov.b64 %0, {%1, %2};" : "=l"(d)
        : "r"(__float_as_uint(lo)), "r"(__float_as_uint(hi)));
    return d;
}
__device__ __forceinline__ float2 unpack2(ull v) {
    unsigned l, h;
    asm("mov.b64 {%0, %1}, %2;" : "=r"(l), "=r"(h) : "l"(v));
    return make_float2(__uint_as_float(l), __uint_as_float(h));
}
__device__ __forceinline__ float dot32p(const ull* a, const ull* b) {
    ull s0 = 0, s1 = 0;
#pragma unroll
    for (int q = 0; q < 16; q += 2) {
        s0 = fma2(a[q],   b[q],   s0);
        s1 = fma2(a[q+1], b[q+1], s1);
    }
    float2 x = unpack2(s0), y = unpack2(s1);
    return (x.x + x.y) + (y.x + y.y);
}

// bf16 hi/lo split
__device__ __forceinline__ void bsplit(float v, __nv_bfloat16& h, __nv_bfloat16& l) {
    h = __float2bfloat16(v);
    l = __float2bfloat16(v - __bfloat162float(h));
}

// bf16 HMMA m16n8k16 (baseline PTX, works on plain sm_103 target)
__device__ __forceinline__ void mma16816(float* c, const uint32_t* a,
                                         uint32_t b0, uint32_t b1) {
    asm volatile(
        "mma.sync.aligned.m16n8k16.row.col.f32.bf16.bf16.f32 "
        "{%0,%1,%2,%3}, {%4,%5,%6,%7}, {%8,%9}, {%0,%1,%2,%3};"
        : "+f"(c[0]), "+f"(c[1]), "+f"(c[2]), "+f"(c[3])
        : "r"(a[0]), "r"(a[1]), "r"(a[2]), "r"(a[3]), "r"(b0), "r"(b1));
}

// ---------------------------------------------------------------------------
// kNN for D=1
__global__ void knn1_kernel(const float* __restrict__ feat, int* __restrict__ kn) {
    const int NT = 256;
    __shared__ float s[NT];
    int cloud = blockIdx.x / (PP / 256);
    int tile  = blockIdx.x % (PP / 256);
    int gi    = cloud * PP + tile * 256 + threadIdx.x;

    float f0 = feat[gi];
    float bd0 = FLT_MAX, bd1 = FLT_MAX, bd2 = FLT_MAX, bd3 = FLT_MAX;
    int   bi0 = 0, bi1 = 0, bi2 = 0, bi3 = 0;

    for (int j0 = 0; j0 < PP; j0 += NT) {
        __syncthreads();
        s[threadIdx.x] = feat[cloud * PP + j0 + threadIdx.x];
        __syncthreads();
        for (int jj = 0; jj < NT; jj++) {
            float df = f0 - s[jj];
            float dist = df * df;
            int j = cloud * PP + j0 + jj;
            if (dist < bd3) {
                if (dist < bd2) {
                    bd3 = bd2; bi3 = bi2;
                    if (dist < bd1) {
                        bd2 = bd1; bi2 = bi1;
                        if (dist < bd0) { bd1 = bd0; bi1 = bi0; bd0 = dist; bi0 = j; }
                        else            { bd1 = dist; bi1 = j; }
                    } else { bd2 = dist; bi2 = j; }
                } else { bd3 = dist; bi3 = j; }
            }
        }
    }
    kn[gi*4+0] = bi0; kn[gi*4+1] = bi1; kn[gi*4+2] = bi2; kn[gi*4+3] = bi3;
}

// kNN for D=32 (packed)
__global__ void knn32_kernel(const float* __restrict__ feat, int stride,
                             int* __restrict__ kn) {
    const int NT = 128;
    __shared__ float s[NT * 32];
    __shared__ float ssq[NT];

    int tid   = threadIdx.x;
    int cloud = blockIdx.x >> 2;
    int tile  = blockIdx.x & 3;
    int gi    = cloud * PP + tile * 256 + tid;

    ull fp[16];
    const float* fi = feat + (long)gi * stride;
#pragma unroll
    for (int q = 0; q < 8; q++) {
        float4 v = *(const float4*)(fi + q * 4);
        fp[2*q]   = pack2(v.x, v.y);
        fp[2*q+1] = pack2(v.z, v.w);
    }
    float sqi = dot32p(fp, fp);

    float bd0 = FLT_MAX, bd1 = FLT_MAX, bd2 = FLT_MAX, bd3 = FLT_MAX;
    int   bi0 = 0, bi1 = 0, bi2 = 0, bi3 = 0;

    for (int j0 = 0; j0 < PP; j0 += NT) {
        __syncthreads();
#pragma unroll
        for (int l = 0; l < 4; l++) {
            int idx = tid + l * 256;
            int row = idx >> 3, c4 = idx & 7;
            *(float4*)&s[row * 32 + c4 * 4] =
                *(const float4*)(feat + (long)(cloud * PP + j0 + row) * stride + c4 * 4);
        }
        __syncthreads();
        if (tid < NT) {
            const ull* sp = (const ull*)&s[tid * 32];
            ull t[16];
#pragma unroll
            for (int q = 0; q < 16; q++) t[q] = sp[q];
            ssq[tid] = dot32p(t, t);
        }
        __syncthreads();

        for (int jj = 0; jj < NT; jj++) {
            const ull* sp = (const ull*)&s[jj * 32];
            ull s0 = 0, s1 = 0;
#pragma unroll
            for (int q = 0; q < 16; q += 2) {
                s0 = fma2(fp[q],   sp[q],   s0);
                s1 = fma2(fp[q+1], sp[q+1], s1);
            }
            float2 x = unpack2(s0), y = unpack2(s1);
            float dot  = (x.x + x.y) + (y.x + y.y);
            float dist = (sqi + ssq[jj]) - 2.0f * dot;
            int   j    = cloud * PP + j0 + jj;
            if (dist < bd3) {
                if (dist < bd2) {
                    bd3 = bd2; bi3 = bi2;
                    if (dist < bd1) {
                        bd2 = bd1; bi2 = bi1;
                        if (dist < bd0) { bd1 = bd0; bi1 = bi0; bd0 = dist; bi0 = j; }
                        else            { bd1 = dist; bi1 = j; }
                    } else { bd2 = dist; bi2 = j; }
                } else { bd3 = dist; bi3 = j; }
            }
        }
    }
    kn[gi*4+0] = bi0; kn[gi*4+1] = bi1; kn[gi*4+2] = bi2; kn[gi*4+3] = bi3;
}

// ---------------------------------------------------------------------------
// Edge conv D=1 (conv1): warp-per-point. Writes fp32 f (stride 64) + bf16 split.
__global__ void edge_conv1_kernel(const float* __restrict__ feat,
                                  const int* __restrict__ kn,
                                  const float* __restrict__ W1, const float* __restrict__ b1,
                                  const float* __restrict__ W2, const float* __restrict__ b2,
                                  float* __restrict__ fo,
                                  __nv_bfloat16* __restrict__ bqh,
                                  __nv_bfloat16* __restrict__ bql) {
    const int C = 32;
    __shared__ float sW1[2 * C];
    __shared__ float sW2[C * C];
    __shared__ float sb1[C], sb2[C];
    __shared__ float sh[8][C];

    int tid = threadIdx.x;
    for (int i = tid; i < 2 * C; i += 256) sW1[i] = W1[i];
    for (int i = tid; i < C * C; i += 256) sW2[i] = W2[i];
    if (tid < C) { sb1[tid] = b1[tid]; sb2[tid] = b2[tid]; }
    __syncthreads();

    int w = tid / 32, lane = tid % 32;
    int pt = blockIdx.x * 8 + w;
    float xi = feat[pt];

    float acc = -FLT_MAX;
#pragma unroll
    for (int k = 0; k < KNN; k++) {
        int j = kn[pt * 4 + k];
        float dj = feat[j] - xi;
        float hv = fmaf(xi, sW1[lane], fmaf(dj, sW1[C + lane], sb1[lane]));
        sh[w][lane] = fmaxf(hv, 0.f);
        __syncwarp();
        float ov = sb2[lane];
#pragma unroll
        for (int t = 0; t < C; t++) ov = fmaf(sh[w][t], sW2[t * C + lane], ov);
        acc = fmaxf(acc, ov);
        __syncwarp();
    }
    fo[(long)pt * 64 + lane] = acc;
    __nv_bfloat16 h, l; bsplit(acc, h, l);
    bqh[(long)pt * 128 + lane] = h;
    bql[(long)pt * 128 + lane] = l;
}

// ---------------------------------------------------------------------------
// Edge conv D=32: thread-per-point (S=1) or 2 threads/point (S=2).
template<int C, int S, bool WF32>
__global__ void __launch_bounds__(128)
edge_conv32(const float* __restrict__ feat, int fstride,
            const int* __restrict__ kn,
            const float* __restrict__ W1, const float* __restrict__ b1,
            const float* __restrict__ W2, const float* __restrict__ b2,
            float* __restrict__ fo, int fostride,
            __nv_bfloat16* __restrict__ bqh,
            __nv_bfloat16* __restrict__ bql) {
    constexpr int E  = 64;
    constexpr int CO = C / S;
    __shared__ float sW1T[C][E];
    __shared__ float sW2[C][C];
    __shared__ float sb1[C];

    int tid = threadIdx.x;
    for (int i = tid; i < E * C; i += 128) sW1T[i % C][i / C] = W1[i];
    for (int i = tid; i < C * C; i += 128) sW2[i / C][i % C] = W2[i];
    for (int i = tid; i < C;     i += 128) sb1[i] = b1[i];
    __syncthreads();

    int thr = blockIdx.x * 128 + tid;
    int pt  = thr / S;
    int off = (thr % S) * CO;

    const float* xi_ptr = feat + (long)pt * fstride;
    ull xip[16];
#pragma unroll
    for (int q = 0; q < 8; q++) {
        float4 v = *(const float4*)(xi_ptr + q * 4);
        xip[2*q]   = pack2(v.x, v.y);
        xip[2*q+1] = pack2(v.z, v.w);
    }
    ull m1 = dup2(-1.0f);

    float omax[CO];
#pragma unroll
    for (int c = 0; c < CO; c++) omax[c] = -FLT_MAX;

#pragma unroll
    for (int k = 0; k < KNN; k++) {
        int j = kn[pt * 4 + k];
        const float* xj_ptr = feat + (long)j * fstride;
        ull dfp[16];
#pragma unroll
        for (int q = 0; q < 8; q++) {
            float4 v = *(const float4*)(xj_ptr + q * 4);
            dfp[2*q]   = fma2(xip[2*q],   m1, pack2(v.x, v.y));
            dfp[2*q+1] = fma2(xip[2*q+1], m1, pack2(v.z, v.w));
        }
        ull oe[CO / 2];
#pragma unroll
        for (int c = 0; c < CO / 2; c++) oe[c] = 0;

        for (int t2 = 0; t2 < C; t2++) {
            const ull* wp = (const ull*)&sW1T[t2][0];
            ull h0 = 0, h1 = 0;
#pragma unroll
            for (int q = 0; q < 16; q += 2) {
                h0 = fma2(xip[q],   wp[q],   h0);
                h1 = fma2(xip[q+1], wp[q+1], h1);
            }
#pragma unroll
            for (int q = 0; q < 16; q += 2) {
                h0 = fma2(dfp[q],   wp[16 + q],   h0);
                h1 = fma2(dfp[q+1], wp[16 + q+1], h1);
            }
            float2 a = unpack2(h0), b = unpack2(h1);
            float hv = sb1[t2] + ((a.x + a.y) + (b.x + b.y));
            hv = fmaxf(hv, 0.0f);
            ull hv2 = dup2(hv);
            const ull* w2p = (const ull*)&sW2[t2][off];
#pragma unroll
            for (int c = 0; c < CO / 2; c++) oe[c] = fma2(hv2, w2p[c], oe[c]);
        }
#pragma unroll
        for (int c = 0; c < CO / 2; c++) {
            float2 p = unpack2(oe[c]);
            omax[2*c]   = fmaxf(omax[2*c],   p.x);
            omax[2*c+1] = fmaxf(omax[2*c+1], p.y);
        }
    }
#pragma unroll
    for (int c = 0; c < CO; c++) {
        float v = omax[c] + b2[off + c];
        if (WF32) fo[(long)pt * fostride + off + c] = v;
        __nv_bfloat16 h, l; bsplit(v, h, l);
        bqh[(long)pt * 128 + off + c] = h;
        bql[(long)pt * 128 + off + c] = l;
    }
}

// ---------------------------------------------------------------------------
// Weight transpose + bf16 split: W[K,264] -> WT_h/l[NP2=272][KP3=288], zero pad
__global__ void wconv_kernel(const float* __restrict__ W, int K,
                             __nv_bfloat16* __restrict__ th,
                             __nv_bfloat16* __restrict__ tl) {
    int idx = blockIdx.x * 256 + threadIdx.x;
    if (idx >= NP2 * KP3) return;
    int n = idx / KP3, k = idx % KP3;
    float v = (n < 264 && k < K) ? W[(long)k * 264 + n] : 0.0f;
    __nv_bfloat16 h, l; bsplit(v, h, l);
    th[idx] = h; tl[idx] = l;
}

// Zero activation K-pad columns [272,288) (cols [264,272) are written as exact
// zeros by the GEMM epilogue via zero weight rows + zero bias)
__global__ void padzero_kernel(__nv_bfloat16* a, __nv_bfloat16* b,
                               __nv_bfloat16* c, __nv_bfloat16* d) {
    int row = blockIdx.x * 256 + threadIdx.x;
    if (row >= NPTS) return;
    uint4 z = make_uint4(0, 0, 0, 0);
    long o = (long)row * KP3 + 272;
    *(uint4*)(a + o) = z; *(uint4*)(a + o + 8) = z;
    *(uint4*)(b + o) = z; *(uint4*)(b + o + 8) = z;
    *(uint4*)(c + o) = z; *(uint4*)(c + o + 8) = z;
    *(uint4*)(d + o) = z; *(uint4*)(d + o + 8) = z;
}

// ---------------------------------------------------------------------------
// HMMA bf16-split GEMM: out[N,272] = relu(A[N,KTOT] @ W + bias), where
// A = Ah+Al bf16 split [N,KTOT], W as transposed split [272][288].
// CTA: 512 thr, tile M=128 x N=272, K chunks of 32 in smem.
// Warp (16 of them): wm = wid&7 -> 16 rows, wn = wid>>3 -> 136 cols (17 tiles).
// EPI 0: bf16-split out (stride KP3); EPI 1: fp32 out (stride KP3).
template<int KTOT, int EPI>
__global__ void __launch_bounds__(512, 1)
gemm_mma(const __nv_bfloat16* __restrict__ Ah, const __nv_bfloat16* __restrict__ Al,
         const __nv_bfloat16* __restrict__ Bh, const __nv_bfloat16* __restrict__ Bl,
         const float* __restrict__ bias,
         __nv_bfloat16* __restrict__ Oh, __nv_bfloat16* __restrict__ Ol,
         float* __restrict__ Of) {
    extern __shared__ char smem[];
    // layout: bias fp32 [272] @0 (1088B); A bf16 [2][128][40] @1088 (20480B);
    //         B bf16 [2][272][40] @21568 (43520B). total 65088B.
    const int OFF_A = 1088;
    const int OFF_B = 21568;
    const int SROW  = 80;      // 40 bf16 per row (bank-conflict-free for frags)

    int tid = threadIdx.x, wid = tid >> 5, lane = tid & 31;
    int m0 = blockIdx.x * 128;
    int wm = wid & 7, wn = wid >> 3;
    int g  = lane >> 2;               // 0..7
    int q  = (lane & 3) * 2;          // 0,2,4,6

    float* bias_s = (float*)smem;
    if (tid < NP2) bias_s[tid] = (tid < 264) ? bias[tid] : 0.0f;

    float acc[17][4];
#pragma unroll
    for (int t = 0; t < 17; t++)
#pragma unroll
        for (int c = 0; c < 4; c++) acc[t][c] = 0.0f;

    const int aRowBase = wm * 16 + g;

    for (int k0 = 0; k0 < KTOT; k0 += 32) {
        __syncthreads();
        // load A: 2 terms x 128 rows x 4 uint4
#pragma unroll
        for (int l = 0; l < 2; l++) {
            int idx = tid + l * 512;                 // 0..1023
            int term = idx >> 9, rem = idx & 511;
            int r = rem >> 2, c4 = rem & 3;
            const __nv_bfloat16* src = (term ? Al : Ah) + (long)(m0 + r) * KTOT + k0 + c4 * 8;
            *(uint4*)(smem + OFF_A + (term * 128 + r) * SROW + c4 * 16) = *(const uint4*)src;
        }
        // load B: 2 terms x 272 rows x 4 uint4 = 2176
        for (int idx = tid; idx < 2176; idx += 512) {
            int term = idx >= 1088;
            int rem  = idx - term * 1088;
            int n = rem >> 2, c4 = rem & 3;
            const __nv_bfloat16* src = (term ? Bl : Bh) + (long)n * KP3 + k0 + c4 * 8;
            *(uint4*)(smem + OFF_B + (term * NP2 + n) * SROW + c4 * 16) = *(const uint4*)src;
        }
        __syncthreads();

#pragma unroll
        for (int s = 0; s < 2; s++) {
            const int kk = s * 16;
            uint32_t aH[4], aL[4];
            {
                int ab = OFF_A + aRowBase * SROW + (kk + q) * 2;
                aH[0] = *(const uint32_t*)(smem + ab);
                aH[1] = *(const uint32_t*)(smem + ab + 8 * SROW);
                aH[2] = *(const uint32_t*)(smem + ab + 16);
                aH[3] = *(const uint32_t*)(smem + ab + 8 * SROW + 16);
                int ab2 = ab + 128 * SROW;
                aL[0] = *(const uint32_t*)(smem + ab2);
                aL[1] = *(const uint32_t*)(smem + ab2 + 8 * SROW);
                aL[2] = *(const uint32_t*)(smem + ab2 + 16);
                aL[3] = *(const uint32_t*)(smem + ab2 + 8 * SROW + 16);
            }
#pragma unroll
            for (int t = 0; t < 17; t++) {
                int n  = wn * 136 + t * 8 + g;
                int bb = OFF_B + n * SROW + (kk + q) * 2;
                uint32_t bh0 = *(const uint32_t*)(smem + bb);
                uint32_t bh1 = *(const uint32_t*)(smem + bb + 16);
                uint32_t bl0 = *(const uint32_t*)(smem + bb + NP2 * SROW);
                uint32_t bl1 = *(const uint32_t*)(smem + bb + NP2 * SROW + 16);
                mma16816(acc[t], aH, bh0, bh1);
                mma16816(acc[t], aH, bl0, bl1);
                mma16816(acc[t], aL, bh0, bh1);
            }
        }
    }

    // epilogue
    int row0 = m0 + wm * 16 + g;
#pragma unroll
    for (int t = 0; t < 17; t++) {
        int c0 = wn * 136 + t * 8 + q;
        float b0 = bias_s[c0], b1 = bias_s[c0 + 1];
        float v00 = fmaxf(acc[t][0] + b0, 0.f);
        float v01 = fmaxf(acc[t][1] + b1, 0.f);
        float v10 = fmaxf(acc[t][2] + b0, 0.f);
        float v11 = fmaxf(acc[t][3] + b1, 0.f);
        if (EPI == 0) {
            __nv_bfloat16 h0, l0, h1, l1;
            bsplit(v00, h0, l0); bsplit(v01, h1, l1);
            uint32_t ph = ((uint32_t)__bfloat16_as_ushort(h1) << 16) | __bfloat16_as_ushort(h0);
            uint32_t pl = ((uint32_t)__bfloat16_as_ushort(l1) << 16) | __bfloat16_as_ushort(l0);
            *(uint32_t*)(Oh + (long)row0 * KP3 + c0) = ph;
            *(uint32_t*)(Ol + (long)row0 * KP3 + c0) = pl;
            bsplit(v10, h0, l0); bsplit(v11, h1, l1);
            ph = ((uint32_t)__bfloat16_as_ushort(h1) << 16) | __bfloat16_as_ushort(h0);
            pl = ((uint32_t)__bfloat16_as_ushort(l1) << 16) | __bfloat16_as_ushort(l0);
            *(uint32_t*)(Oh + (long)(row0 + 8) * KP3 + c0) = ph;
            *(uint32_t*)(Ol + (long)(row0 + 8) * KP3 + c0) = pl;
        } else {
            *(float2*)(Of + (long)row0 * KP3 + c0)       = make_float2(v00, v01);
            *(float2*)(Of + (long)(row0 + 8) * KP3 + c0) = make_float2(v10, v11);
        }
    }
}

// ---------------------------------------------------------------------------
// Final 264->2 linear + log_softmax. One warp per point. H stride = KP3.
__global__ void final_kernel(const float* __restrict__ H, const float* __restrict__ W4,
                             const float* __restrict__ b4, float* __restrict__ out, int N) {
    int warp = (blockIdx.x * blockDim.x + threadIdx.x) / 32;
    int lane = threadIdx.x % 32;
    if (warp >= N) return;
    const float* h = H + (long)warp * KP3;
    float s0 = 0.f, s1 = 0.f;
    for (int t = lane; t < 264; t += 32) {
        float hv = h[t];
        s0 = fmaf(hv, W4[t * 2 + 0], s0);
        s1 = fmaf(hv, W4[t * 2 + 1], s1);
    }
#pragma unroll
    for (int o = 16; o > 0; o >>= 1) {
        s0 += __shfl_xor_sync(0xFFFFFFFFu, s0, o);
        s1 += __shfl_xor_sync(0xFFFFFFFFu, s1, o);
    }
    if (lane == 0) {
        float o0 = s0 + b4[0], o1 = s1 + b4[1];
        float m = fmaxf(o0, o1);
        float lse = m + logf(expf(o0 - m) + expf(o1 - m));
        out[warp * 2 + 0] = o0 - lse;
        out[warp * 2 + 1] = o1 - lse;
    }
}

// ---------------------------------------------------------------------------
extern "C" void kernel_launch(void* const* d_in, const int* in_sizes, int n_in,
                              void* d_out, int out_size) {
    const float* x    = (const float*)d_in[0];
    const float* c1W1 = (const float*)d_in[2];
    const float* c1b1 = (const float*)d_in[3];
    const float* c1W2 = (const float*)d_in[4];
    const float* c1b2 = (const float*)d_in[5];
    const float* c2W1 = (const float*)d_in[6];
    const float* c2b1 = (const float*)d_in[7];
    const float* c2W2 = (const float*)d_in[8];
    const float* c2b2 = (const float*)d_in[9];
    const float* c3W1 = (const float*)d_in[10];
    const float* c3b1 = (const float*)d_in[11];
    const float* c3W2 = (const float*)d_in[12];
    const float* c3b2 = (const float*)d_in[13];
    const float* mW1  = (const float*)d_in[14];
    const float* mb1  = (const float*)d_in[15];
    const float* mW2  = (const float*)d_in[16];
    const float* mb2  = (const float*)d_in[17];
    const float* mW3  = (const float*)d_in[18];
    const float* mb3  = (const float*)d_in[19];
    const float* mW4  = (const float*)d_in[20];
    const float* mb4  = (const float*)d_in[21];
    float* out = (float*)d_out;

    float *f, *h3; int* knn;
    __nv_bfloat16 *fah, *fal, *xah, *xal, *yah, *yal, *wh, *wl;
    cudaGetSymbolAddress((void**)&f,   g_f);
    cudaGetSymbolAddress((void**)&h3,  g_h3);
    cudaGetSymbolAddress((void**)&knn, g_knn);
    cudaGetSymbolAddress((void**)&fah, g_fa_h);
    cudaGetSymbolAddress((void**)&fal, g_fa_l);
    cudaGetSymbolAddress((void**)&xah, g_xa_h);
    cudaGetSymbolAddress((void**)&xal, g_xa_l);
    cudaGetSymbolAddress((void**)&yah, g_ya_h);
    cudaGetSymbolAddress((void**)&yal, g_ya_l);
    cudaGetSymbolAddress((void**)&wh,  g_w_h);
    cudaGetSymbolAddress((void**)&wl,  g_w_l);

    const int SMEM_GEMM = 65088;
    cudaFuncSetAttribute(gemm_mma<128, 0>, cudaFuncAttributeMaxDynamicSharedMemorySize, SMEM_GEMM);
    cudaFuncSetAttribute(gemm_mma<KP3, 0>, cudaFuncAttributeMaxDynamicSharedMemorySize, SMEM_GEMM);
    cudaFuncSetAttribute(gemm_mma<KP3, 1>, cudaFuncAttributeMaxDynamicSharedMemorySize, SMEM_GEMM);

    const int knn_blocks = BC * (PP / 256);   // 512

    // setup: weight transpose/split + activation K-pad zeroing
    padzero_kernel<<<NPTS / 256, 256>>>(xah, xal, yah, yal);
    wconv_kernel<<<(NP2 * KP3 + 255) / 256, 256>>>(mW1, 128, wh + 0 * NP2 * KP3, wl + 0 * NP2 * KP3);
    wconv_kernel<<<(NP2 * KP3 + 255) / 256, 256>>>(mW2, 264, wh + 1 * NP2 * KP3, wl + 1 * NP2 * KP3);
    wconv_kernel<<<(NP2 * KP3 + 255) / 256, 256>>>(mW3, 264, wh + 2 * NP2 * KP3, wl + 2 * NP2 * KP3);

    // conv1: d=1 -> c=32 (cols 0..31)
    knn1_kernel<<<knn_blocks, 256>>>(x, knn);
    edge_conv1_kernel<<<NPTS / 8, 256>>>(x, knn, c1W1, c1b1, c1W2, c1b2, f, fah, fal);
    // conv2: d=32 -> c=32 (cols 32..63)
    knn32_kernel<<<knn_blocks, 256>>>(f, 64, knn);
    edge_conv32<32, 1, true><<<NPTS / 128, 128>>>(f, 64, knn, c2W1, c2b1, c2W2, c2b2,
                                                  f + 32, 64, fah + 32, fal + 32);
    // conv3: d=32 -> c=64 (cols 64..127)
    knn32_kernel<<<knn_blocks, 256>>>(f + 32, 64, knn);
    edge_conv32<64, 2, false><<<2 * NPTS / 128, 128>>>(f + 32, 64, knn, c3W1, c3b1, c3W2, c3b2,
                                                       nullptr, 0, fah + 64, fal + 64);

    // final MLP via HMMA bf16-split GEMMs
    dim3 gg(NPTS / 128);
    gemm_mma<128, 0><<<gg, 512, SMEM_GEMM>>>(fah, fal, wh + 0 * NP2 * KP3, wl + 0 * NP2 * KP3,
                                             mb1, xah, xal, nullptr);
    gemm_mma<KP3, 0><<<gg, 512, SMEM_GEMM>>>(xah, xal, wh + 1 * NP2 * KP3, wl + 1 * NP2 * KP3,
                                             mb2, yah, yal, nullptr);
    gemm_mma<KP3, 1><<<gg, 512, SMEM_GEMM>>>(yah, yal, wh + 2 * NP2 * KP3, wl + 2 * NP2 * KP3,
                                             mb3, nullptr, nullptr, h3);
    final_kernel<<<NPTS / 8, 256>>>(h3, mW4, mb4, out, NPTS);
}

// round 10
// speedup vs baseline: 1.7333x; 1.1769x over previous
#include <cuda_runtime.h>
#include <cuda_bf16.h>
#include <float.h>
#include <math.h>
#include <stdint.h>

// Problem constants
#define BC   128
#define PP   1024
#define NPTS (BC*PP)   // 131072
#define KNN  4
#define KP3  288       // K padded to 288 (9 chunks of 32); N padded to 272
#define NP2  272

typedef unsigned long long ull;

// ---------------------------------------------------------------------------
// Scratch (device globals; no allocation allowed)
__device__ float          g_f   [NPTS * 64];        // fp32 [x1|x2] for kNN (stride 64)
__device__ __nv_bfloat16  g_fa_h[NPTS * 128];       // bf16-hi concat feats, fragment-permuted
__device__ __nv_bfloat16  g_fa_l[NPTS * 128];
__device__ __nv_bfloat16  g_xa_h[NPTS * KP3];       // h1 split, fragment-permuted
__device__ __nv_bfloat16  g_xa_l[NPTS * KP3];
__device__ __nv_bfloat16  g_ya_h[NPTS * KP3];       // h2 split, fragment-permuted
__device__ __nv_bfloat16  g_ya_l[NPTS * KP3];
__device__ __nv_bfloat16  g_w_h [3][NP2 * KP3];     // transposed split weights, permuted
__device__ __nv_bfloat16  g_w_l [3][NP2 * KP3];
__device__ int            g_knn [NPTS * KNN];

// ---------------------------------------------------------------------------
// Fragment-permuted element offset: within each 16-k block, granule
// ((k>>1)&3)^(r&3) holds elements (2q2, 2q2+1, 2q2+8, 2q2+9).
__device__ __forceinline__ long permoff(int r, int k, int stride) {
    int blk = k >> 4;
    int q2  = (k >> 1) & 3;
    int hi  = (k >> 3) & 1;
    int gr  = q2 ^ (r & 3);
    return (long)r * stride + blk * 16 + gr * 4 + hi * 2 + (k & 1);
}

// ---------------------------------------------------------------------------
// packed f32x2 helpers (for SIMT kernels)
__device__ __forceinline__ ull fma2(ull a, ull b, ull c) {
    ull d; asm("fma.rn.f32x2 %0, %1, %2, %3;" : "=l"(d) : "l"(a), "l"(b), "l"(c));
    return d;
}
__device__ __forceinline__ ull dup2(float x) {
    ull d; unsigned u = __float_as_uint(x);
    asm("mov.b64 %0, {%1, %1};" : "=l"(d) : "r"(u));
    return d;
}
__device__ __forceinline__ ull pack2(float lo, float hi) {
    ull d;
    asm("mov.b64 %0, {%1, %2};" : "=l"(d)
        : "r"(__float_as_uint(lo)), "r"(__float_as_uint(hi)));
    return d;
}
__device__ __forceinline__ float2 unpack2(ull v) {
    unsigned l, h;
    asm("mov.b64 {%0, %1}, %2;" : "=r"(l), "=r"(h) : "l"(v));
    return make_float2(__uint_as_float(l), __uint_as_float(h));
}
__device__ __forceinline__ float dot32p(const ull* a, const ull* b) {
    ull s0 = 0, s1 = 0;
#pragma unroll
    for (int q = 0; q < 16; q += 2) {
        s0 = fma2(a[q],   b[q],   s0);
        s1 = fma2(a[q+1], b[q+1], s1);
    }
    float2 x = unpack2(s0), y = unpack2(s1);
    return (x.x + x.y) + (y.x + y.y);
}
__device__ __forceinline__ void bsplit(float v, __nv_bfloat16& h, __nv_bfloat16& l) {
    h = __float2bfloat16(v);
    l = __float2bfloat16(v - __bfloat162float(h));
}

// bf16 HMMA m16n8k16
__device__ __forceinline__ void mma16816(float* c, const uint32_t* a,
                                         uint32_t b0, uint32_t b1) {
    asm volatile(
        "mma.sync.aligned.m16n8k16.row.col.f32.bf16.bf16.f32 "
        "{%0,%1,%2,%3}, {%4,%5,%6,%7}, {%8,%9}, {%0,%1,%2,%3};"
        : "+f"(c[0]), "+f"(c[1]), "+f"(c[2]), "+f"(c[3])
        : "r"(a[0]), "r"(a[1]), "r"(a[2]), "r"(a[3]), "r"(b0), "r"(b1));
}

__device__ __forceinline__ uint32_t smem_u32(const void* p) {
    uint32_t a;
    asm("{ .reg .u64 t; cvta.to.shared.u64 t, %1; cvt.u32.u64 %0, t; }"
        : "=r"(a) : "l"(p));
    return a;
}
__device__ __forceinline__ uint2 lds64(uint32_t addr) {
    uint2 v;
    asm volatile("ld.shared.v2.u32 {%0,%1}, [%2];" : "=r"(v.x), "=r"(v.y) : "r"(addr));
    return v;
}
__device__ __forceinline__ void cp16(uint32_t saddr, const void* gaddr) {
    asm volatile("cp.async.cg.shared.global [%0], [%1], 16;" :: "r"(saddr), "l"(gaddr));
}
#define CP_COMMIT() asm volatile("cp.async.commit_group;" ::: "memory")
#define CP_WAIT1()  asm volatile("cp.async.wait_group 1;" ::: "memory")
#define CP_WAIT0()  asm volatile("cp.async.wait_group 0;" ::: "memory")

// ---------------------------------------------------------------------------
// kNN for D=1
__global__ void knn1_kernel(const float* __restrict__ feat, int* __restrict__ kn) {
    const int NT = 256;
    __shared__ float s[NT];
    int cloud = blockIdx.x / (PP / 256);
    int tile  = blockIdx.x % (PP / 256);
    int gi    = cloud * PP + tile * 256 + threadIdx.x;

    float f0 = feat[gi];
    float bd0 = FLT_MAX, bd1 = FLT_MAX, bd2 = FLT_MAX, bd3 = FLT_MAX;
    int   bi0 = 0, bi1 = 0, bi2 = 0, bi3 = 0;

    for (int j0 = 0; j0 < PP; j0 += NT) {
        __syncthreads();
        s[threadIdx.x] = feat[cloud * PP + j0 + threadIdx.x];
        __syncthreads();
        for (int jj = 0; jj < NT; jj++) {
            float df = f0 - s[jj];
            float dist = df * df;
            int j = cloud * PP + j0 + jj;
            if (dist < bd3) {
                if (dist < bd2) {
                    bd3 = bd2; bi3 = bi2;
                    if (dist < bd1) {
                        bd2 = bd1; bi2 = bi1;
                        if (dist < bd0) { bd1 = bd0; bi1 = bi0; bd0 = dist; bi0 = j; }
                        else            { bd1 = dist; bi1 = j; }
                    } else { bd2 = dist; bi2 = j; }
                } else { bd3 = dist; bi3 = j; }
            }
        }
    }
    kn[gi*4+0] = bi0; kn[gi*4+1] = bi1; kn[gi*4+2] = bi2; kn[gi*4+3] = bi3;
}

// kNN for D=32 (packed f32x2)
__global__ void knn32_kernel(const float* __restrict__ feat, int stride,
                             int* __restrict__ kn) {
    const int NT = 128;
    __shared__ float s[NT * 32];
    __shared__ float ssq[NT];

    int tid   = threadIdx.x;
    int cloud = blockIdx.x >> 2;
    int tile  = blockIdx.x & 3;
    int gi    = cloud * PP + tile * 256 + tid;

    ull fp[16];
    const float* fi = feat + (long)gi * stride;
#pragma unroll
    for (int q = 0; q < 8; q++) {
        float4 v = *(const float4*)(fi + q * 4);
        fp[2*q]   = pack2(v.x, v.y);
        fp[2*q+1] = pack2(v.z, v.w);
    }
    float sqi = dot32p(fp, fp);

    float bd0 = FLT_MAX, bd1 = FLT_MAX, bd2 = FLT_MAX, bd3 = FLT_MAX;
    int   bi0 = 0, bi1 = 0, bi2 = 0, bi3 = 0;

    for (int j0 = 0; j0 < PP; j0 += NT) {
        __syncthreads();
#pragma unroll
        for (int l = 0; l < 4; l++) {
            int idx = tid + l * 256;
            int row = idx >> 3, c4 = idx & 7;
            *(float4*)&s[row * 32 + c4 * 4] =
                *(const float4*)(feat + (long)(cloud * PP + j0 + row) * stride + c4 * 4);
        }
        __syncthreads();
        if (tid < NT) {
            const ull* sp = (const ull*)&s[tid * 32];
            ull t[16];
#pragma unroll
            for (int q = 0; q < 16; q++) t[q] = sp[q];
            ssq[tid] = dot32p(t, t);
        }
        __syncthreads();

        for (int jj = 0; jj < NT; jj++) {
            const ull* sp = (const ull*)&s[jj * 32];
            ull s0 = 0, s1 = 0;
#pragma unroll
            for (int q = 0; q < 16; q += 2) {
                s0 = fma2(fp[q],   sp[q],   s0);
                s1 = fma2(fp[q+1], sp[q+1], s1);
            }
            float2 x = unpack2(s0), y = unpack2(s1);
            float dot  = (x.x + x.y) + (y.x + y.y);
            float dist = (sqi + ssq[jj]) - 2.0f * dot;
            int   j    = cloud * PP + j0 + jj;
            if (dist < bd3) {
                if (dist < bd2) {
                    bd3 = bd2; bi3 = bi2;
                    if (dist < bd1) {
                        bd2 = bd1; bi2 = bi1;
                        if (dist < bd0) { bd1 = bd0; bi1 = bi0; bd0 = dist; bi0 = j; }
                        else            { bd1 = dist; bi1 = j; }
                    } else { bd2 = dist; bi2 = j; }
                } else { bd3 = dist; bi3 = j; }
            }
        }
    }
    kn[gi*4+0] = bi0; kn[gi*4+1] = bi1; kn[gi*4+2] = bi2; kn[gi*4+3] = bi3;
}

// ---------------------------------------------------------------------------
// Edge conv D=1: warp-per-point. fp32 f (stride 64) + permuted bf16 split (cols 0..31).
__global__ void edge_conv1_kernel(const float* __restrict__ feat,
                                  const int* __restrict__ kn,
                                  const float* __restrict__ W1, const float* __restrict__ b1,
                                  const float* __restrict__ W2, const float* __restrict__ b2,
                                  float* __restrict__ fo,
                                  __nv_bfloat16* __restrict__ bqh,
                                  __nv_bfloat16* __restrict__ bql) {
    const int C = 32;
    __shared__ float sW1[2 * C];
    __shared__ float sW2[C * C];
    __shared__ float sb1[C], sb2[C];
    __shared__ float sh[8][C];

    int tid = threadIdx.x;
    for (int i = tid; i < 2 * C; i += 256) sW1[i] = W1[i];
    for (int i = tid; i < C * C; i += 256) sW2[i] = W2[i];
    if (tid < C) { sb1[tid] = b1[tid]; sb2[tid] = b2[tid]; }
    __syncthreads();

    int w = tid / 32, lane = tid % 32;
    int pt = blockIdx.x * 8 + w;
    float xi = feat[pt];

    float acc = -FLT_MAX;
#pragma unroll
    for (int k = 0; k < KNN; k++) {
        int j = kn[pt * 4 + k];
        float dj = feat[j] - xi;
        float hv = fmaf(xi, sW1[lane], fmaf(dj, sW1[C + lane], sb1[lane]));
        sh[w][lane] = fmaxf(hv, 0.f);
        __syncwarp();
        float ov = sb2[lane];
#pragma unroll
        for (int t = 0; t < C; t++) ov = fmaf(sh[w][t], sW2[t * C + lane], ov);
        acc = fmaxf(acc, ov);
        __syncwarp();
    }
    fo[(long)pt * 64 + lane] = acc;
    __nv_bfloat16 h, l; bsplit(acc, h, l);
    long o = permoff(pt, lane, 128);
    bqh[o] = h;
    bql[o] = l;
}

// ---------------------------------------------------------------------------
// Edge conv D=32: thread-per-point (S=1) or 2 threads/point (S=2).
// Permuted bf16 split written at feature columns [colbase, colbase+C).
template<int C, int S, bool WF32>
__global__ void __launch_bounds__(128)
edge_conv32(const float* __restrict__ feat, int fstride,
            const int* __restrict__ kn,
            const float* __restrict__ W1, const float* __restrict__ b1,
            const float* __restrict__ W2, const float* __restrict__ b2,
            float* __restrict__ fo, int fostride, int colbase,
            __nv_bfloat16* __restrict__ bqh,
            __nv_bfloat16* __restrict__ bql) {
    constexpr int E  = 64;
    constexpr int CO = C / S;
    __shared__ float sW1T[C][E];
    __shared__ float sW2[C][C];
    __shared__ float sb1[C];

    int tid = threadIdx.x;
    for (int i = tid; i < E * C; i += 128) sW1T[i % C][i / C] = W1[i];
    for (int i = tid; i < C * C; i += 128) sW2[i / C][i % C] = W2[i];
    for (int i = tid; i < C;     i += 128) sb1[i] = b1[i];
    __syncthreads();

    int thr = blockIdx.x * 128 + tid;
    int pt  = thr / S;
    int off = (thr % S) * CO;

    const float* xi_ptr = feat + (long)pt * fstride;
    ull xip[16];
#pragma unroll
    for (int q = 0; q < 8; q++) {
        float4 v = *(const float4*)(xi_ptr + q * 4);
        xip[2*q]   = pack2(v.x, v.y);
        xip[2*q+1] = pack2(v.z, v.w);
    }
    ull m1 = dup2(-1.0f);

    float omax[CO];
#pragma unroll
    for (int c = 0; c < CO; c++) omax[c] = -FLT_MAX;

#pragma unroll
    for (int k = 0; k < KNN; k++) {
        int j = kn[pt * 4 + k];
        const float* xj_ptr = feat + (long)j * fstride;
        ull dfp[16];
#pragma unroll
        for (int q = 0; q < 8; q++) {
            float4 v = *(const float4*)(xj_ptr + q * 4);
            dfp[2*q]   = fma2(xip[2*q],   m1, pack2(v.x, v.y));
            dfp[2*q+1] = fma2(xip[2*q+1], m1, pack2(v.z, v.w));
        }
        ull oe[CO / 2];
#pragma unroll
        for (int c = 0; c < CO / 2; c++) oe[c] = 0;

        for (int t2 = 0; t2 < C; t2++) {
            const ull* wp = (const ull*)&sW1T[t2][0];
            ull h0 = 0, h1 = 0;
#pragma unroll
            for (int q = 0; q < 16; q += 2) {
                h0 = fma2(xip[q],   wp[q],   h0);
                h1 = fma2(xip[q+1], wp[q+1], h1);
            }
#pragma unroll
            for (int q = 0; q < 16; q += 2) {
                h0 = fma2(dfp[q],   wp[16 + q],   h0);
                h1 = fma2(dfp[q+1], wp[16 + q+1], h1);
            }
            float2 a = unpack2(h0), b = unpack2(h1);
            float hv = sb1[t2] + ((a.x + a.y) + (b.x + b.y));
            hv = fmaxf(hv, 0.0f);
            ull hv2 = dup2(hv);
            const ull* w2p = (const ull*)&sW2[t2][off];
#pragma unroll
            for (int c = 0; c < CO / 2; c++) oe[c] = fma2(hv2, w2p[c], oe[c]);
        }
#pragma unroll
        for (int c = 0; c < CO / 2; c++) {
            float2 p = unpack2(oe[c]);
            omax[2*c]   = fmaxf(omax[2*c],   p.x);
            omax[2*c+1] = fmaxf(omax[2*c+1], p.y);
        }
    }
#pragma unroll
    for (int c = 0; c < CO / 2; c++) {
        int col = off + 2 * c;
        float v0 = omax[2*c]   + b2[col];
        float v1 = omax[2*c+1] + b2[col + 1];
        if (WF32) {
            fo[(long)pt * fostride + col]     = v0;
            fo[(long)pt * fostride + col + 1] = v1;
        }
        __nv_bfloat16 h0, l0, h1, l1;
        bsplit(v0, h0, l0); bsplit(v1, h1, l1);
        uint32_t ph = ((uint32_t)__bfloat16_as_ushort(h1) << 16) | __bfloat16_as_ushort(h0);
        uint32_t pl = ((uint32_t)__bfloat16_as_ushort(l1) << 16) | __bfloat16_as_ushort(l0);
        long o = permoff(pt, colbase + col, 128);
        *(uint32_t*)(bqh + o) = ph;
        *(uint32_t*)(bql + o) = pl;
    }
}

// ---------------------------------------------------------------------------
// Weight transpose + split to permuted layout: W[K,264] -> [NP2][KP3]
__global__ void wconv_kernel(const float* __restrict__ W, int K,
                             __nv_bfloat16* __restrict__ th,
                             __nv_bfloat16* __restrict__ tl) {
    int idx = blockIdx.x * 256 + threadIdx.x;
    if (idx >= NP2 * KP3) return;
    int n = idx / KP3, k = idx % KP3;
    float v = (n < 264 && k < K) ? W[(long)k * 264 + n] : 0.0f;
    __nv_bfloat16 h, l; bsplit(v, h, l);
    long o = permoff(n, k, KP3);
    th[o] = h; tl[o] = l;
}

// Zero activation K-pad blocks [272,288)
__global__ void padzero_kernel(__nv_bfloat16* a, __nv_bfloat16* b,
                               __nv_bfloat16* c, __nv_bfloat16* d) {
    int row = blockIdx.x * 256 + threadIdx.x;
    if (row >= NPTS) return;
    uint4 z = make_uint4(0, 0, 0, 0);
    long o = (long)row * KP3 + 272;
    *(uint4*)(a + o) = z; *(uint4*)(a + o + 8) = z;
    *(uint4*)(b + o) = z; *(uint4*)(b + o + 8) = z;
    *(uint4*)(c + o) = z; *(uint4*)(c + o + 8) = z;
    *(uint4*)(d + o) = z; *(uint4*)(d + o + 8) = z;
}

// ---------------------------------------------------------------------------
// HMMA bf16-split GEMM, cp.async double-buffered, conflict-free fragment smem.
// CTA: 512 thr, tile M=128 x N=272 (17 n-tiles x 16 warps), K chunks of 32.
// EPI 0: permuted bf16-split out (stride KP3).
// EPI 2: fused 264->2 linear + log_softmax -> Out fp32 [N][2].
template<int KTOT, int EPI>
__global__ void __launch_bounds__(512, 1)
gemm_mma(const __nv_bfloat16* __restrict__ Ah, const __nv_bfloat16* __restrict__ Al,
         const __nv_bfloat16* __restrict__ Bh, const __nv_bfloat16* __restrict__ Bl,
         const float* __restrict__ bias,
         __nv_bfloat16* __restrict__ Oh, __nv_bfloat16* __restrict__ Ol,
         const float* __restrict__ W4, const float* __restrict__ b4,
         float* __restrict__ Out) {
    extern __shared__ char smem[];
    const int OFF_W4 = 1088, OFF_RED = 3264, OFF_A = 5312, OFF_B = 54464;
    const int ABUF = 24576, ATERM = 12288, BBUF = 52224, BTERM = 26112;

    uint32_t sb = smem_u32(smem);
    int tid = threadIdx.x, wid = tid >> 5, lane = tid & 31;
    int m0 = blockIdx.x * 128;
    int wm = wid & 7, wn = wid >> 3;
    int g  = lane >> 2;               // 0..7
    int qi = lane & 3;                // 0..3
    int q  = qi * 2;

    float* bias_s = (float*)smem;
    if (tid < NP2) bias_s[tid] = (tid < 264) ? bias[tid] : 0.0f;
    if (EPI == 2) {
        float* w4s = (float*)(smem + OFF_W4);
        for (int i = tid; i < 544; i += 512) w4s[i] = (i < 528) ? W4[i] : 0.0f;
    }

    float acc[17][4];
#pragma unroll
    for (int t = 0; t < 17; t++)
#pragma unroll
        for (int c = 0; c < 4; c++) acc[t][c] = 0.0f;

    constexpr int NCH = KTOT / 32;

    auto stage = [&](int buf, int k0) {
#pragma unroll
        for (int l = 0; l < 2; l++) {
            int idx = tid + l * 512;
            int term = idx >> 9, rem = idx & 511;
            int r = rem >> 2, c = rem & 3;
            const __nv_bfloat16* src =
                (term ? Al : Ah) + (long)(m0 + r) * KTOT + k0 + c * 8;
            cp16(sb + OFF_A + buf * ABUF + term * ATERM + r * 96 + c * 16, src);
        }
        for (int idx = tid; idx < 2176; idx += 512) {
            int term = idx >= 1088;
            int rem  = idx - term * 1088;
            int n = rem >> 2, c = rem & 3;
            const __nv_bfloat16* src =
                (term ? Bl : Bh) + (long)n * KP3 + k0 + c * 8;
            cp16(sb + OFF_B + buf * BBUF + term * BTERM + n * 96 + c * 16, src);
        }
    };

    stage(0, 0);
    CP_COMMIT();

    const uint32_t frOff = (uint32_t)((qi ^ (g & 3)) << 3);
    const int rb = wm * 16 + g;

    for (int ch = 0; ch < NCH; ch++) {
        if (ch + 1 < NCH) {
            stage((ch + 1) & 1, (ch + 1) * 32);
            CP_COMMIT();
            CP_WAIT1();
        } else {
            CP_WAIT0();
        }
        __syncthreads();
        int buf = ch & 1;
        uint32_t aBase = sb + OFF_A + buf * ABUF;
        uint32_t bBase = sb + OFF_B + buf * BBUF;

#pragma unroll
        for (int s = 0; s < 2; s++) {
            uint32_t ao = (uint32_t)(rb * 96 + s * 32) + frOff;
            uint2 aHlo = lds64(aBase + ao);
            uint2 aHhi = lds64(aBase + ao + 8 * 96);
            uint2 aLlo = lds64(aBase + ATERM + ao);
            uint2 aLhi = lds64(aBase + ATERM + ao + 8 * 96);
            uint32_t aH[4] = { aHlo.x, aHhi.x, aHlo.y, aHhi.y };
            uint32_t aL[4] = { aLlo.x, aLhi.x, aLlo.y, aLhi.y };
#pragma unroll
            for (int t = 0; t < 17; t++) {
                int n = wn * 136 + t * 8 + g;
                uint32_t bo = (uint32_t)(n * 96 + s * 32) + frOff;
                uint2 bh = lds64(bBase + bo);
                uint2 bl = lds64(bBase + BTERM + bo);
                mma16816(acc[t], aH, bh.x, bh.y);
                mma16816(acc[t], aH, bl.x, bl.y);
                mma16816(acc[t], aL, bh.x, bh.y);
            }
        }
        __syncthreads();
    }

    // ---------------- epilogue ----------------
    int row0 = m0 + wm * 16 + g;
    if (EPI == 0) {
#pragma unroll
        for (int t = 0; t < 17; t++) {
            int c0 = wn * 136 + t * 8 + q;
            float b0 = bias_s[c0], b1 = bias_s[c0 + 1];
            float v00 = fmaxf(acc[t][0] + b0, 0.f);
            float v01 = fmaxf(acc[t][1] + b1, 0.f);
            float v10 = fmaxf(acc[t][2] + b0, 0.f);
            float v11 = fmaxf(acc[t][3] + b1, 0.f);
            __nv_bfloat16 h0, l0, h1, l1;
            bsplit(v00, h0, l0); bsplit(v01, h1, l1);
            uint32_t ph = ((uint32_t)__bfloat16_as_ushort(h1) << 16) | __bfloat16_as_ushort(h0);
            uint32_t pl = ((uint32_t)__bfloat16_as_ushort(l1) << 16) | __bfloat16_as_ushort(l0);
            long o = permoff(row0, c0, KP3);
            *(uint32_t*)(Oh + o) = ph;
            *(uint32_t*)(Ol + o) = pl;
            bsplit(v10, h0, l0); bsplit(v11, h1, l1);
            ph = ((uint32_t)__bfloat16_as_ushort(h1) << 16) | __bfloat16_as_ushort(h0);
            pl = ((uint32_t)__bfloat16_as_ushort(l1) << 16) | __bfloat16_as_ushort(l0);
            long o2 = permoff(row0 + 8, c0, KP3);
            *(uint32_t*)(Oh + o2) = ph;
            *(uint32_t*)(Ol + o2) = pl;
        }
    } else {
        const float* w4s = (const float*)(smem + OFF_W4);
        float p00 = 0.f, p01 = 0.f, p10 = 0.f, p11 = 0.f;
#pragma unroll
        for (int t = 0; t < 17; t++) {
            int c0 = wn * 136 + t * 8 + q;
            float b0 = bias_s[c0], b1 = bias_s[c0 + 1];
            float v00 = fmaxf(acc[t][0] + b0, 0.f);
            float v01 = fmaxf(acc[t][1] + b1, 0.f);
            float v10 = fmaxf(acc[t][2] + b0, 0.f);
            float v11 = fmaxf(acc[t][3] + b1, 0.f);
            float w00 = w4s[c0 * 2],       w01 = w4s[c0 * 2 + 1];
            float w10 = w4s[(c0 + 1) * 2], w11 = w4s[(c0 + 1) * 2 + 1];
            p00 = fmaf(v00, w00, fmaf(v01, w10, p00));
            p01 = fmaf(v00, w01, fmaf(v01, w11, p01));
            p10 = fmaf(v10, w00, fmaf(v11, w10, p10));
            p11 = fmaf(v10, w01, fmaf(v11, w11, p11));
        }
#pragma unroll
        for (int o = 1; o < 4; o <<= 1) {
            p00 += __shfl_xor_sync(0xFFFFFFFFu, p00, o);
            p01 += __shfl_xor_sync(0xFFFFFFFFu, p01, o);
            p10 += __shfl_xor_sync(0xFFFFFFFFu, p10, o);
            p11 += __shfl_xor_sync(0xFFFFFFFFu, p11, o);
        }
        float* red = (float*)(smem + OFF_RED);
        if (qi == 0) {
            int r = wm * 16 + g;
            red[(wn * 128 + r) * 2 + 0]     = p00;
            red[(wn * 128 + r) * 2 + 1]     = p01;
            red[(wn * 128 + r + 8) * 2 + 0] = p10;
            red[(wn * 128 + r + 8) * 2 + 1] = p11;
        }
        __syncthreads();
        if (tid < 128) {
            float o0 = red[tid * 2 + 0] + red[(128 + tid) * 2 + 0] + b4[0];
            float o1 = red[tid * 2 + 1] + red[(128 + tid) * 2 + 1] + b4[1];
            float m = fmaxf(o0, o1);
            float lse = m + logf(expf(o0 - m) + expf(o1 - m));
            Out[(long)(m0 + tid) * 2 + 0] = o0 - lse;
            Out[(long)(m0 + tid) * 2 + 1] = o1 - lse;
        }
    }
}

// ---------------------------------------------------------------------------
extern "C" void kernel_launch(void* const* d_in, const int* in_sizes, int n_in,
                              void* d_out, int out_size) {
    const float* x    = (const float*)d_in[0];
    const float* c1W1 = (const float*)d_in[2];
    const float* c1b1 = (const float*)d_in[3];
    const float* c1W2 = (const float*)d_in[4];
    const float* c1b2 = (const float*)d_in[5];
    const float* c2W1 = (const float*)d_in[6];
    const float* c2b1 = (const float*)d_in[7];
    const float* c2W2 = (const float*)d_in[8];
    const float* c2b2 = (const float*)d_in[9];
    const float* c3W1 = (const float*)d_in[10];
    const float* c3b1 = (const float*)d_in[11];
    const float* c3W2 = (const float*)d_in[12];
    const float* c3b2 = (const float*)d_in[13];
    const float* mW1  = (const float*)d_in[14];
    const float* mb1  = (const float*)d_in[15];
    const float* mW2  = (const float*)d_in[16];
    const float* mb2  = (const float*)d_in[17];
    const float* mW3  = (const float*)d_in[18];
    const float* mb3  = (const float*)d_in[19];
    const float* mW4  = (const float*)d_in[20];
    const float* mb4  = (const float*)d_in[21];
    float* out = (float*)d_out;

    float* f; int* knn;
    __nv_bfloat16 *fah, *fal, *xah, *xal, *yah, *yal, *wh, *wl;
    cudaGetSymbolAddress((void**)&f,   g_f);
    cudaGetSymbolAddress((void**)&knn, g_knn);
    cudaGetSymbolAddress((void**)&fah, g_fa_h);
    cudaGetSymbolAddress((void**)&fal, g_fa_l);
    cudaGetSymbolAddress((void**)&xah, g_xa_h);
    cudaGetSymbolAddress((void**)&xal, g_xa_l);
    cudaGetSymbolAddress((void**)&yah, g_ya_h);
    cudaGetSymbolAddress((void**)&yal, g_ya_l);
    cudaGetSymbolAddress((void**)&wh,  g_w_h);
    cudaGetSymbolAddress((void**)&wl,  g_w_l);

    const int SMEM_GEMM = 158912;
    cudaFuncSetAttribute(gemm_mma<128, 0>, cudaFuncAttributeMaxDynamicSharedMemorySize, SMEM_GEMM);
    cudaFuncSetAttribute(gemm_mma<KP3, 0>, cudaFuncAttributeMaxDynamicSharedMemorySize, SMEM_GEMM);
    cudaFuncSetAttribute(gemm_mma<KP3, 2>, cudaFuncAttributeMaxDynamicSharedMemorySize, SMEM_GEMM);

    const int knn_blocks = BC * (PP / 256);   // 512

    // setup
    padzero_kernel<<<NPTS / 256, 256>>>(xah, xal, yah, yal);
    wconv_kernel<<<(NP2 * KP3 + 255) / 256, 256>>>(mW1, 128, wh + 0 * NP2 * KP3, wl + 0 * NP2 * KP3);
    wconv_kernel<<<(NP2 * KP3 + 255) / 256, 256>>>(mW2, 264, wh + 1 * NP2 * KP3, wl + 1 * NP2 * KP3);
    wconv_kernel<<<(NP2 * KP3 + 255) / 256, 256>>>(mW3, 264, wh + 2 * NP2 * KP3, wl + 2 * NP2 * KP3);

    // conv1: d=1 -> c=32 (cols 0..31)
    knn1_kernel<<<knn_blocks, 256>>>(x, knn);
    edge_conv1_kernel<<<NPTS / 8, 256>>>(x, knn, c1W1, c1b1, c1W2, c1b2, f, fah, fal);
    // conv2: d=32 -> c=32 (cols 32..63)
    knn32_kernel<<<knn_blocks, 256>>>(f, 64, knn);
    edge_conv32<32, 1, true><<<NPTS / 128, 128>>>(f, 64, knn, c2W1, c2b1, c2W2, c2b2,
                                                  f + 32, 64, 32, fah, fal);
    // conv3: d=32 -> c=64 (cols 64..127)
    knn32_kernel<<<knn_blocks, 256>>>(f + 32, 64, knn);
    edge_conv32<64, 2, false><<<2 * NPTS / 128, 128>>>(f + 32, 64, knn, c3W1, c3b1, c3W2, c3b2,
                                                       nullptr, 0, 64, fah, fal);

    // final MLP via double-buffered HMMA GEMMs (GEMM3 fuses final layer)
    dim3 gg(NPTS / 128);
    gemm_mma<128, 0><<<gg, 512, SMEM_GEMM>>>(fah, fal, wh + 0 * NP2 * KP3, wl + 0 * NP2 * KP3,
                                             mb1, xah, xal, nullptr, nullptr, nullptr);
    gemm_mma<KP3, 0><<<gg, 512, SMEM_GEMM>>>(xah, xal, wh + 1 * NP2 * KP3, wl + 1 * NP2 * KP3,
                                             mb2, yah, yal, nullptr, nullptr, nullptr);
    gemm_mma<KP3, 2><<<gg, 512, SMEM_GEMM>>>(yah, yal, wh + 2 * NP2 * KP3, wl + 2 * NP2 * KP3,
                                             mb3, nullptr, nullptr, mW4, mb4, out);
}

// round 12
// speedup vs baseline: 1.7928x; 1.0344x over previous
#include <cuda_runtime.h>
#include <cuda_bf16.h>
#include <float.h>
#include <math.h>
#include <stdint.h>

// Problem constants
#define BC   128
#define PP   1024
#define NPTS (BC*PP)   // 131072
#define KNN  4
#define KP3  288       // K padded to 288 (9 chunks of 32); N padded to 272
#define NP2  272

typedef unsigned long long ull;

// ---------------------------------------------------------------------------
// Scratch (device globals; no allocation allowed)
__device__ float          g_f   [NPTS * 64];        // fp32 [x1|x2] for edge convs (stride 64)
__device__ float          g_sq  [NPTS];             // per-point squared norms (bf16-split consistent)
__device__ __nv_bfloat16  g_fa_h[NPTS * 128];       // bf16-hi concat feats, fragment-permuted
__device__ __nv_bfloat16  g_fa_l[NPTS * 128];
__device__ __nv_bfloat16  g_xa_h[NPTS * KP3];       // h1 split, fragment-permuted
__device__ __nv_bfloat16  g_xa_l[NPTS * KP3];
__device__ __nv_bfloat16  g_ya_h[NPTS * KP3];       // h2 split, fragment-permuted
__device__ __nv_bfloat16  g_ya_l[NPTS * KP3];
__device__ __nv_bfloat16  g_w_h [3][NP2 * KP3];     // transposed split weights, permuted
__device__ __nv_bfloat16  g_w_l [3][NP2 * KP3];
__device__ int            g_knn [NPTS * KNN];

// ---------------------------------------------------------------------------
// Fragment-permuted element offset: within each 16-k block, granule
// ((k>>1)&3)^(r&3) holds elements (2q2, 2q2+1, 2q2+8, 2q2+9).
__device__ __forceinline__ long permoff(int r, int k, int stride) {
    int blk = k >> 4;
    int q2  = (k >> 1) & 3;
    int hi  = (k >> 3) & 1;
    int gr  = q2 ^ (r & 3);
    return (long)r * stride + blk * 16 + gr * 4 + hi * 2 + (k & 1);
}

// ---------------------------------------------------------------------------
// packed f32x2 helpers (for SIMT kernels)
__device__ __forceinline__ ull fma2(ull a, ull b, ull c) {
    ull d; asm("fma.rn.f32x2 %0, %1, %2, %3;" : "=l"(d) : "l"(a), "l"(b), "l"(c));
    return d;
}
__device__ __forceinline__ ull dup2(float x) {
    ull d; unsigned u = __float_as_uint(x);
    asm("mov.b64 %0, {%1, %1};" : "=l"(d) : "r"(u));
    return d;
}
__device__ __forceinline__ ull pack2(float lo, float hi) {
    ull d;
    asm("mov.b64 %0, {%1, %2};" : "=l"(d)
        : "r"(__float_as_uint(lo)), "r"(__float_as_uint(hi)));
    return d;
}
__device__ __forceinline__ float2 unpack2(ull v) {
    unsigned l, h;
    asm("mov.b64 {%0, %1}, %2;" : "=r"(l), "=r"(h) : "l"(v));
    return make_float2(__uint_as_float(l), __uint_as_float(h));
}
__device__ __forceinline__ void bsplit(float v, __nv_bfloat16& h, __nv_bfloat16& l) {
    h = __float2bfloat16(v);
    l = __float2bfloat16(v - __bfloat162float(h));
}

// bf16 HMMA m16n8k16
__device__ __forceinline__ void mma16816(float* c, const uint32_t* a,
                                         uint32_t b0, uint32_t b1) {
    asm volatile(
        "mma.sync.aligned.m16n8k16.row.col.f32.bf16.bf16.f32 "
        "{%0,%1,%2,%3}, {%4,%5,%6,%7}, {%8,%9}, {%0,%1,%2,%3};"
        : "+f"(c[0]), "+f"(c[1]), "+f"(c[2]), "+f"(c[3])
        : "r"(a[0]), "r"(a[1]), "r"(a[2]), "r"(a[3]), "r"(b0), "r"(b1));
}

__device__ __forceinline__ uint32_t smem_u32(const void* p) {
    uint32_t a;
    asm("{ .reg .u64 t; cvta.to.shared.u64 t, %1; cvt.u32.u64 %0, t; }"
        : "=r"(a) : "l"(p));
    return a;
}
__device__ __forceinline__ uint2 lds64(uint32_t addr) {
    uint2 v;
    asm volatile("ld.shared.v2.u32 {%0,%1}, [%2];" : "=r"(v.x), "=r"(v.y) : "r"(addr));
    return v;
}
__device__ __forceinline__ void cp16(uint32_t saddr, const void* gaddr) {
    asm volatile("cp.async.cg.shared.global [%0], [%1], 16;" :: "r"(saddr), "l"(gaddr));
}
#define CP_COMMIT() asm volatile("cp.async.commit_group;" ::: "memory")
#define CP_WAIT1()  asm volatile("cp.async.wait_group 1;" ::: "memory")
#define CP_WAIT0()  asm volatile("cp.async.wait_group 0;" ::: "memory")

// top-4 insertion ladder (strict <, earliest-seen wins ties)
__device__ __forceinline__ void lad4(float* bs, int* bi, float s, int id) {
    if (s < bs[3]) {
        if (s < bs[2]) {
            bs[3] = bs[2]; bi[3] = bi[2];
            if (s < bs[1]) {
                bs[2] = bs[1]; bi[2] = bi[1];
                if (s < bs[0]) { bs[1] = bs[0]; bi[1] = bi[0]; bs[0] = s; bi[0] = id; }
                else           { bs[1] = s; bi[1] = id; }
            } else { bs[2] = s; bi[2] = id; }
        } else { bs[3] = s; bi[3] = id; }
    }
}

// ---------------------------------------------------------------------------
// kNN for D=1 (exact fp32; input feature space)
__global__ void knn1_kernel(const float* __restrict__ feat, int* __restrict__ kn) {
    const int NT = 256;
    __shared__ float s[NT];
    int cloud = blockIdx.x / (PP / 256);
    int tile  = blockIdx.x % (PP / 256);
    int gi    = cloud * PP + tile * 256 + threadIdx.x;

    float f0 = feat[gi];
    float bd[4] = { FLT_MAX, FLT_MAX, FLT_MAX, FLT_MAX };
    int   bi[4] = { 0, 0, 0, 0 };

    for (int j0 = 0; j0 < PP; j0 += NT) {
        __syncthreads();
        s[threadIdx.x] = feat[cloud * PP + j0 + threadIdx.x];
        __syncthreads();
        for (int jj = 0; jj < NT; jj++) {
            float df = f0 - s[jj];
            lad4(bd, bi, df * df, cloud * PP + j0 + jj);
        }
    }
    kn[gi*4+0] = bi[0]; kn[gi*4+1] = bi[1]; kn[gi*4+2] = bi[2]; kn[gi*4+3] = bi[3];
}

// ---------------------------------------------------------------------------
// Squared norms from the bf16 hi/lo split (consistent with the kNN Gram MMA).
// kb0 = starting 16-k block (0 for cols 0..31, 2 for cols 32..63).
__global__ void sqnorm_kernel(const __nv_bfloat16* __restrict__ Fh,
                              const __nv_bfloat16* __restrict__ Fl,
                              int kb0, float* __restrict__ sq) {
    int p = blockIdx.x * 256 + threadIdx.x;
    if (p >= NPTS) return;
    const __nv_bfloat16* ph = Fh + (long)p * 128 + kb0 * 16;
    const __nv_bfloat16* pl = Fl + (long)p * 128 + kb0 * 16;
    float s = 0.f;
#pragma unroll
    for (int i = 0; i < 32; i++) {
        float v = __bfloat162float(ph[i]) + __bfloat162float(pl[i]);
        s = fmaf(v, v, s);
    }
    sq[p] = s;
}

// ---------------------------------------------------------------------------
// Fused HMMA kNN (D=32): per CTA 64 queries x 1024 candidates of one cloud.
// 3-term bf16-split Gram via mma; rank by sq_j - 2*dot_ij; in-register top-4
// ladders merged through smem. Operands read from the fragment-permuted
// bf16 feature buffers (stride 128), k-blocks [kb0, kb0+2).
__global__ void __launch_bounds__(256, 2)
knn_mma(const __nv_bfloat16* __restrict__ Fh, const __nv_bfloat16* __restrict__ Fl,
        int kb0, const float* __restrict__ sq, int* __restrict__ kn) {
    extern __shared__ char smem[];
    const int OFF_A  = 0;              // 2 terms * 64 rows * 96B = 12288
    const int OFF_B  = 12288;          // 2 terms * 256 rows * 96B = 49152
    const int OFF_SQ = 61440;          // 256 floats = 1024
    const int OFF_MG = 12288;          // merge buffer (reuses B region, 32KB)
    const int ATERM  = 64 * 96;        // 6144
    const int BTERM  = 256 * 96;       // 24576

    uint32_t sb = smem_u32(smem);
    int tid = threadIdx.x, wid = tid >> 5, lane = tid & 31;
    int cloud = blockIdx.x >> 4;
    int qbase = (blockIdx.x & 15) * 64;
    int gq    = cloud * PP + qbase;    // global query row base
    int gc0   = cloud * PP;            // candidate base
    int wm = wid >> 2, wn = wid & 3;   // 2 m-warps x 4 n-warps
    int g  = lane >> 2, qi = lane & 3, q = qi * 2;

    // stage A (query rows), once
    for (int idx = tid; idx < 512; idx += 256) {
        int term = idx >> 8, rem = idx & 255;
        int r = rem >> 2, c = rem & 3;
        const __nv_bfloat16* src =
            (term ? Fl : Fh) + (long)(gq + r) * 128 + (kb0 + (c >> 1)) * 16 + (c & 1) * 8;
        cp16(sb + OFF_A + term * ATERM + r * 96 + c * 16, src);
    }
    CP_COMMIT();

    // 4 ladders per thread: rows wm*32 + mt*16 + h*8 + g (mt,h in {0,1})
    float bs[4][4]; int bi[4][4];
#pragma unroll
    for (int a = 0; a < 4; a++)
#pragma unroll
        for (int b = 0; b < 4; b++) { bs[a][b] = FLT_MAX; bi[a][b] = 0; }

    const uint32_t frOff = (uint32_t)((qi ^ (g & 3)) << 3);

    for (int nc = 0; nc < 4; nc++) {
        int cb = nc * 256;
        __syncthreads();   // previous chunk fully consumed
        for (int idx = tid; idx < 2048; idx += 256) {
            int term = idx >> 10, rem = idx & 1023;
            int r = rem >> 2, c = rem & 3;
            const __nv_bfloat16* src =
                (term ? Fl : Fh) + (long)(gc0 + cb + r) * 128 + (kb0 + (c >> 1)) * 16 + (c & 1) * 8;
            cp16(sb + OFF_B + term * BTERM + r * 96 + c * 16, src);
        }
        if (tid < 64)
            cp16(sb + OFF_SQ + tid * 16, sq + gc0 + cb + tid * 4);
        CP_COMMIT();
        CP_WAIT0();
        __syncthreads();

        const float* ssq = (const float*)(smem + OFF_SQ);
#pragma unroll
        for (int mt = 0; mt < 2; mt++) {
            float acc[8][4];
#pragma unroll
            for (int nt = 0; nt < 8; nt++)
#pragma unroll
                for (int c = 0; c < 4; c++) acc[nt][c] = 0.0f;

#pragma unroll
            for (int s = 0; s < 2; s++) {
                uint32_t ao = (uint32_t)((wm * 32 + mt * 16 + g) * 96 + s * 32) + frOff;
                uint2 aHlo = lds64(sb + OFF_A + ao);
                uint2 aHhi = lds64(sb + OFF_A + ao + 8 * 96);
                uint2 aLlo = lds64(sb + OFF_A + ATERM + ao);
                uint2 aLhi = lds64(sb + OFF_A + ATERM + ao + 8 * 96);
                uint32_t aH[4] = { aHlo.x, aHhi.x, aHlo.y, aHhi.y };
                uint32_t aL[4] = { aLlo.x, aLhi.x, aLlo.y, aLhi.y };
#pragma unroll
                for (int nt = 0; nt < 8; nt++) {
                    int n = wn * 64 + nt * 8 + g;
                    uint32_t bo = (uint32_t)(n * 96 + s * 32) + frOff;
                    uint2 bh = lds64(sb + OFF_B + bo);
                    uint2 bl = lds64(sb + OFF_B + BTERM + bo);
                    mma16816(acc[nt], aH, bh.x, bh.y);
                    mma16816(acc[nt], aH, bl.x, bl.y);
                    mma16816(acc[nt], aL, bh.x, bh.y);
                }
            }
            // score + ladder update
#pragma unroll
            for (int nt = 0; nt < 8; nt++) {
                int col = wn * 64 + nt * 8 + q;
                float sj0 = ssq[col], sj1 = ssq[col + 1];
#pragma unroll
                for (int h = 0; h < 2; h++) {
                    int li = mt * 2 + h;
                    lad4(bs[li], bi[li], sj0 - 2.0f * acc[nt][h*2+0], cb + col);
                    lad4(bs[li], bi[li], sj1 - 2.0f * acc[nt][h*2+1], cb + col + 1);
                }
            }
        }
    }

    // merge: 16 partial lists per query row
    __syncthreads();
    float2* mg = (float2*)(smem + OFF_MG);   // [row][src][4] as (score, idx-bits)
    int src = wn * 4 + qi;
#pragma unroll
    for (int mt = 0; mt < 2; mt++)
#pragma unroll
        for (int h = 0; h < 2; h++) {
            int row = wm * 32 + mt * 16 + h * 8 + g;
            int li = mt * 2 + h;
#pragma unroll
            for (int k = 0; k < 4; k++)
                mg[(row * 16 + src) * 4 + k] =
                    make_float2(bs[li][k], __int_as_float(bi[li][k]));
        }
    __syncthreads();
    if (tid < 64) {
        float fs[4] = { FLT_MAX, FLT_MAX, FLT_MAX, FLT_MAX };
        int   fi[4] = { 0, 0, 0, 0 };
        const float2* rowp = mg + tid * 64;
        for (int e = 0; e < 64; e++) {
            float2 p = rowp[(e + tid) & 63];   // rotated start (bank spread)
            lad4(fs, fi, p.x, __float_as_int(p.y));
        }
        int gpt = gq + tid;
#pragma unroll
        for (int k = 0; k < 4; k++) kn[gpt * 4 + k] = gc0 + fi[k];
    }
}

// ---------------------------------------------------------------------------
// Edge conv D=1: warp-per-point. fp32 f (stride 64) + permuted bf16 split (cols 0..31).
__global__ void edge_conv1_kernel(const float* __restrict__ feat,
                                  const int* __restrict__ kn,
                                  const float* __restrict__ W1, const float* __restrict__ b1,
                                  const float* __restrict__ W2, const float* __restrict__ b2,
                                  float* __restrict__ fo,
                                  __nv_bfloat16* __restrict__ bqh,
                                  __nv_bfloat16* __restrict__ bql) {
    const int C = 32;
    __shared__ float sW1[2 * C];
    __shared__ float sW2[C * C];
    __shared__ float sb1[C], sb2[C];
    __shared__ float sh[8][C];

    int tid = threadIdx.x;
    for (int i = tid; i < 2 * C; i += 256) sW1[i] = W1[i];
    for (int i = tid; i < C * C; i += 256) sW2[i] = W2[i];
    if (tid < C) { sb1[tid] = b1[tid]; sb2[tid] = b2[tid]; }
    __syncthreads();

    int w = tid / 32, lane = tid % 32;
    int pt = blockIdx.x * 8 + w;
    float xi = feat[pt];

    float acc = -FLT_MAX;
#pragma unroll
    for (int k = 0; k < KNN; k++) {
        int j = kn[pt * 4 + k];
        float dj = feat[j] - xi;
        float hv = fmaf(xi, sW1[lane], fmaf(dj, sW1[C + lane], sb1[lane]));
        sh[w][lane] = fmaxf(hv, 0.f);
        __syncwarp();
        float ov = sb2[lane];
#pragma unroll
        for (int t = 0; t < C; t++) ov = fmaf(sh[w][t], sW2[t * C + lane], ov);
        acc = fmaxf(acc, ov);
        __syncwarp();
    }
    fo[(long)pt * 64 + lane] = acc;
    __nv_bfloat16 h, l; bsplit(acc, h, l);
    long o = permoff(pt, lane, 128);
    bqh[o] = h;
    bql[o] = l;
}

// ---------------------------------------------------------------------------
// Edge conv D=32: thread-per-point (S=1) or 2 threads/point (S=2).
// Permuted bf16 split written at feature columns [colbase, colbase+C).
template<int C, int S, bool WF32>
__global__ void __launch_bounds__(128)
edge_conv32(const float* __restrict__ feat, int fstride,
            const int* __restrict__ kn,
            const float* __restrict__ W1, const float* __restrict__ b1,
            const float* __restrict__ W2, const float* __restrict__ b2,
            float* __restrict__ fo, int fostride, int colbase,
            __nv_bfloat16* __restrict__ bqh,
            __nv_bfloat16* __restrict__ bql) {
    constexpr int E  = 64;
    constexpr int CO = C / S;
    __shared__ float sW1T[C][E];
    __shared__ float sW2[C][C];
    __shared__ float sb1[C];

    int tid = threadIdx.x;
    for (int i = tid; i < E * C; i += 128) sW1T[i % C][i / C] = W1[i];
    for (int i = tid; i < C * C; i += 128) sW2[i / C][i % C] = W2[i];
    for (int i = tid; i < C;     i += 128) sb1[i] = b1[i];
    __syncthreads();

    int thr = blockIdx.x * 128 + tid;
    int pt  = thr / S;
    int off = (thr % S) * CO;

    const float* xi_ptr = feat + (long)pt * fstride;
    ull xip[16];
#pragma unroll
    for (int q = 0; q < 8; q++) {
        float4 v = *(const float4*)(xi_ptr + q * 4);
        xip[2*q]   = pack2(v.x, v.y);
        xip[2*q+1] = pack2(v.z, v.w);
    }
    ull m1 = dup2(-1.0f);

    float omax[CO];
#pragma unroll
    for (int c = 0; c < CO; c++) omax[c] = -FLT_MAX;

#pragma unroll
    for (int k = 0; k < KNN; k++) {
        int j = kn[pt * 4 + k];
        const float* xj_ptr = feat + (long)j * fstride;
        ull dfp[16];
#pragma unroll
        for (int q = 0; q < 8; q++) {
            float4 v = *(const float4*)(xj_ptr + q * 4);
            dfp[2*q]   = fma2(xip[2*q],   m1, pack2(v.x, v.y));
            dfp[2*q+1] = fma2(xip[2*q+1], m1, pack2(v.z, v.w));
        }
        ull oe[CO / 2];
#pragma unroll
        for (int c = 0; c < CO / 2; c++) oe[c] = 0;

        for (int t2 = 0; t2 < C; t2++) {
            const ull* wp = (const ull*)&sW1T[t2][0];
            ull h0 = 0, h1 = 0;
#pragma unroll
            for (int q = 0; q < 16; q += 2) {
                h0 = fma2(xip[q],   wp[q],   h0);
                h1 = fma2(xip[q+1], wp[q+1], h1);
            }
#pragma unroll
            for (int q = 0; q < 16; q += 2) {
                h0 = fma2(dfp[q],   wp[16 + q],   h0);
                h1 = fma2(dfp[q+1], wp[16 + q+1], h1);
            }
            float2 a = unpack2(h0), b = unpack2(h1);
            float hv = sb1[t2] + ((a.x + a.y) + (b.x + b.y));
            hv = fmaxf(hv, 0.0f);
            ull hv2 = dup2(hv);
            const ull* w2p = (const ull*)&sW2[t2][off];
#pragma unroll
            for (int c = 0; c < CO / 2; c++) oe[c] = fma2(hv2, w2p[c], oe[c]);
        }
#pragma unroll
        for (int c = 0; c < CO / 2; c++) {
            float2 p = unpack2(oe[c]);
            omax[2*c]   = fmaxf(omax[2*c],   p.x);
            omax[2*c+1] = fmaxf(omax[2*c+1], p.y);
        }
    }
#pragma unroll
    for (int c = 0; c < CO / 2; c++) {
        int col = off + 2 * c;
        float v0 = omax[2*c]   + b2[col];
        float v1 = omax[2*c+1] + b2[col + 1];
        if (WF32) {
            fo[(long)pt * fostride + col]     = v0;
            fo[(long)pt * fostride + col + 1] = v1;
        }
        __nv_bfloat16 h0, l0, h1, l1;
        bsplit(v0, h0, l0); bsplit(v1, h1, l1);
        uint32_t ph = ((uint32_t)__bfloat16_as_ushort(h1) << 16) | __bfloat16_as_ushort(h0);
        uint32_t pl = ((uint32_t)__bfloat16_as_ushort(l1) << 16) | __bfloat16_as_ushort(l0);
        long o = permoff(pt, colbase + col, 128);
        *(uint32_t*)(bqh + o) = ph;
        *(uint32_t*)(bql + o) = pl;
    }
}

// ---------------------------------------------------------------------------
// Weight transpose + split to permuted layout: W[K,264] -> [NP2][KP3]
__global__ void wconv_kernel(const float* __restrict__ W, int K,
                             __nv_bfloat16* __restrict__ th,
                             __nv_bfloat16* __restrict__ tl) {
    int idx = blockIdx.x * 256 + threadIdx.x;
    if (idx >= NP2 * KP3) return;
    int n = idx / KP3, k = idx % KP3;
    float v = (n < 264 && k < K) ? W[(long)k * 264 + n] : 0.0f;
    __nv_bfloat16 h, l; bsplit(v, h, l);
    long o = permoff(n, k, KP3);
    th[o] = h; tl[o] = l;
}

// Zero activation K-pad blocks [272,288)
__global__ void padzero_kernel(__nv_bfloat16* a, __nv_bfloat16* b,
                               __nv_bfloat16* c, __nv_bfloat16* d) {
    int row = blockIdx.x * 256 + threadIdx.x;
    if (row >= NPTS) return;
    uint4 z = make_uint4(0, 0, 0, 0);
    long o = (long)row * KP3 + 272;
    *(uint4*)(a + o) = z; *(uint4*)(a + o + 8) = z;
    *(uint4*)(b + o) = z; *(uint4*)(b + o + 8) = z;
    *(uint4*)(c + o) = z; *(uint4*)(c + o + 8) = z;
    *(uint4*)(d + o) = z; *(uint4*)(d + o + 8) = z;
}

// ---------------------------------------------------------------------------
// HMMA bf16-split GEMM, cp.async double-buffered, conflict-free fragment smem.
// EPI 0: permuted bf16-split out (stride KP3).
// EPI 2: fused 264->2 linear + log_softmax -> Out fp32 [N][2].
template<int KTOT, int EPI>
__global__ void __launch_bounds__(512, 1)
gemm_mma(const __nv_bfloat16* __restrict__ Ah, const __nv_bfloat16* __restrict__ Al,
         const __nv_bfloat16* __restrict__ Bh, const __nv_bfloat16* __restrict__ Bl,
         const float* __restrict__ bias,
         __nv_bfloat16* __restrict__ Oh, __nv_bfloat16* __restrict__ Ol,
         const float* __restrict__ W4, const float* __restrict__ b4,
         float* __restrict__ Out) {
    extern __shared__ char smem[];
    const int OFF_W4 = 1088, OFF_RED = 3264, OFF_A = 5312, OFF_B = 54464;
    const int ABUF = 24576, ATERM = 12288, BBUF = 52224, BTERM = 26112;

    uint32_t sb = smem_u32(smem);
    int tid = threadIdx.x, wid = tid >> 5, lane = tid & 31;
    int m0 = blockIdx.x * 128;
    int wm = wid & 7, wn = wid >> 3;
    int g  = lane >> 2;
    int qi = lane & 3;
    int q  = qi * 2;

    float* bias_s = (float*)smem;
    if (tid < NP2) bias_s[tid] = (tid < 264) ? bias[tid] : 0.0f;
    if (EPI == 2) {
        float* w4s = (float*)(smem + OFF_W4);
        for (int i = tid; i < 544; i += 512) w4s[i] = (i < 528) ? W4[i] : 0.0f;
    }

    float acc[17][4];
#pragma unroll
    for (int t = 0; t < 17; t++)
#pragma unroll
        for (int c = 0; c < 4; c++) acc[t][c] = 0.0f;

    constexpr int NCH = KTOT / 32;

    auto stage = [&](int buf, int k0) {
#pragma unroll
        for (int l = 0; l < 2; l++) {
            int idx = tid + l * 512;
            int term = idx >> 9, rem = idx & 511;
            int r = rem >> 2, c = rem & 3;
            const __nv_bfloat16* src =
                (term ? Al : Ah) + (long)(m0 + r) * KTOT + k0 + c * 8;
            cp16(sb + OFF_A + buf * ABUF + term * ATERM + r * 96 + c * 16, src);
        }
        for (int idx = tid; idx < 2176; idx += 512) {
            int term = idx >= 1088;
            int rem  = idx - term * 1088;
            int n = rem >> 2, c = rem & 3;
            const __nv_bfloat16* src =
                (term ? Bl : Bh) + (long)n * KP3 + k0 + c * 8;
            cp16(sb + OFF_B + buf * BBUF + term * BTERM + n * 96 + c * 16, src);
        }
    };

    stage(0, 0);
    CP_COMMIT();

    const uint32_t frOff = (uint32_t)((qi ^ (g & 3)) << 3);
    const int rb = wm * 16 + g;

    for (int ch = 0; ch < NCH; ch++) {
        if (ch + 1 < NCH) {
            stage((ch + 1) & 1, (ch + 1) * 32);
            CP_COMMIT();
            CP_WAIT1();
        } else {
            CP_WAIT0();
        }
        __syncthreads();
        int buf = ch & 1;
        uint32_t aBase = sb + OFF_A + buf * ABUF;
        uint32_t bBase = sb + OFF_B + buf * BBUF;

#pragma unroll
        for (int s = 0; s < 2; s++) {
            uint32_t ao = (uint32_t)(rb * 96 + s * 32) + frOff;
            uint2 aHlo = lds64(aBase + ao);
            uint2 aHhi = lds64(aBase + ao + 8 * 96);
            uint2 aLlo = lds64(aBase + ATERM + ao);
            uint2 aLhi = lds64(aBase + ATERM + ao + 8 * 96);
            uint32_t aH[4] = { aHlo.x, aHhi.x, aHlo.y, aHhi.y };
            uint32_t aL[4] = { aLlo.x, aLhi.x, aLlo.y, aLhi.y };
#pragma unroll
            for (int t = 0; t < 17; t++) {
                int n = wn * 136 + t * 8 + g;
                uint32_t bo = (uint32_t)(n * 96 + s * 32) + frOff;
                uint2 bh = lds64(bBase + bo);
                uint2 bl = lds64(bBase + BTERM + bo);
                mma16816(acc[t], aH, bh.x, bh.y);
                mma16816(acc[t], aH, bl.x, bl.y);
                mma16816(acc[t], aL, bh.x, bh.y);
            }
        }
        __syncthreads();
    }

    int row0 = m0 + wm * 16 + g;
    if (EPI == 0) {
#pragma unroll
        for (int t = 0; t < 17; t++) {
            int c0 = wn * 136 + t * 8 + q;
            float b0 = bias_s[c0], b1 = bias_s[c0 + 1];
            float v00 = fmaxf(acc[t][0] + b0, 0.f);
            float v01 = fmaxf(acc[t][1] + b1, 0.f);
            float v10 = fmaxf(acc[t][2] + b0, 0.f);
            float v11 = fmaxf(acc[t][3] + b1, 0.f);
            __nv_bfloat16 h0, l0, h1, l1;
            bsplit(v00, h0, l0); bsplit(v01, h1, l1);
            uint32_t ph = ((uint32_t)__bfloat16_as_ushort(h1) << 16) | __bfloat16_as_ushort(h0);
            uint32_t pl = ((uint32_t)__bfloat16_as_ushort(l1) << 16) | __bfloat16_as_ushort(l0);
            long o = permoff(row0, c0, KP3);
            *(uint32_t*)(Oh + o) = ph;
            *(uint32_t*)(Ol + o) = pl;
            bsplit(v10, h0, l0); bsplit(v11, h1, l1);
            ph = ((uint32_t)__bfloat16_as_ushort(h1) << 16) | __bfloat16_as_ushort(h0);
            pl = ((uint32_t)__bfloat16_as_ushort(l1) << 16) | __bfloat16_as_ushort(l0);
            long o2 = permoff(row0 + 8, c0, KP3);
            *(uint32_t*)(Oh + o2) = ph;
            *(uint32_t*)(Ol + o2) = pl;
        }
    } else {
        const float* w4s = (const float*)(smem + OFF_W4);
        float p00 = 0.f, p01 = 0.f, p10 = 0.f, p11 = 0.f;
#pragma unroll
        for (int t = 0; t < 17; t++) {
            int c0 = wn * 136 + t * 8 + q;
            float b0 = bias_s[c0], b1 = bias_s[c0 + 1];
            float v00 = fmaxf(acc[t][0] + b0, 0.f);
            float v01 = fmaxf(acc[t][1] + b1, 0.f);
            float v10 = fmaxf(acc[t][2] + b0, 0.f);
            float v11 = fmaxf(acc[t][3] + b1, 0.f);
            float w00 = w4s[c0 * 2],       w01 = w4s[c0 * 2 + 1];
            float w10 = w4s[(c0 + 1) * 2], w11 = w4s[(c0 + 1) * 2 + 1];
            p00 = fmaf(v00, w00, fmaf(v01, w10, p00));
            p01 = fmaf(v00, w01, fmaf(v01, w11, p01));
            p10 = fmaf(v10, w00, fmaf(v11, w10, p10));
            p11 = fmaf(v10, w01, fmaf(v11, w11, p11));
        }
#pragma unroll
        for (int o = 1; o < 4; o <<= 1) {
            p00 += __shfl_xor_sync(0xFFFFFFFFu, p00, o);
            p01 += __shfl_xor_sync(0xFFFFFFFFu, p01, o);
            p10 += __shfl_xor_sync(0xFFFFFFFFu, p10, o);
            p11 += __shfl_xor_sync(0xFFFFFFFFu, p11, o);
        }
        float* red = (float*)(smem + OFF_RED);
        if (qi == 0) {
            int r = wm * 16 + g;
            red[(wn * 128 + r) * 2 + 0]     = p00;
            red[(wn * 128 + r) * 2 + 1]     = p01;
            red[(wn * 128 + r + 8) * 2 + 0] = p10;
            red[(wn * 128 + r + 8) * 2 + 1] = p11;
        }
        __syncthreads();
        if (tid < 128) {
            float o0 = red[tid * 2 + 0] + red[(128 + tid) * 2 + 0] + b4[0];
            float o1 = red[tid * 2 + 1] + red[(128 + tid) * 2 + 1] + b4[1];
            float m = fmaxf(o0, o1);
            float lse = m + logf(expf(o0 - m) + expf(o1 - m));
            Out[(long)(m0 + tid) * 2 + 0] = o0 - lse;
            Out[(long)(m0 + tid) * 2 + 1] = o1 - lse;
        }
    }
}

// ---------------------------------------------------------------------------
extern "C" void kernel_launch(void* const* d_in, const int* in_sizes, int n_in,
                              void* d_out, int out_size) {
    const float* x    = (const float*)d_in[0];
    const float* c1W1 = (const float*)d_in[2];
    const float* c1b1 = (const float*)d_in[3];
    const float* c1W2 = (const float*)d_in[4];
    const float* c1b2 = (const float*)d_in[5];
    const float* c2W1 = (const float*)d_in[6];
    const float* c2b1 = (const float*)d_in[7];
    const float* c2W2 = (const float*)d_in[8];
    const float* c2b2 = (const float*)d_in[9];
    const float* c3W1 = (const float*)d_in[10];
    const float* c3b1 = (const float*)d_in[11];
    const float* c3W2 = (const float*)d_in[12];
    const float* c3b2 = (const float*)d_in[13];
    const float* mW1  = (const float*)d_in[14];
    const float* mb1  = (const float*)d_in[15];
    const float* mW2  = (const float*)d_in[16];
    const float* mb2  = (const float*)d_in[17];
    const float* mW3  = (const float*)d_in[18];
    const float* mb3  = (const float*)d_in[19];
    const float* mW4  = (const float*)d_in[20];
    const float* mb4  = (const float*)d_in[21];
    float* out = (float*)d_out;

    float *f, *sq; int* knn;
    __nv_bfloat16 *fah, *fal, *xah, *xal, *yah, *yal, *wh, *wl;
    cudaGetSymbolAddress((void**)&f,   g_f);
    cudaGetSymbolAddress((void**)&sq,  g_sq);
    cudaGetSymbolAddress((void**)&knn, g_knn);
    cudaGetSymbolAddress((void**)&fah, g_fa_h);
    cudaGetSymbolAddress((void**)&fal, g_fa_l);
    cudaGetSymbolAddress((void**)&xah, g_xa_h);
    cudaGetSymbolAddress((void**)&xal, g_xa_l);
    cudaGetSymbolAddress((void**)&yah, g_ya_h);
    cudaGetSymbolAddress((void**)&yal, g_ya_l);
    cudaGetSymbolAddress((void**)&wh,  g_w_h);
    cudaGetSymbolAddress((void**)&wl,  g_w_l);

    const int SMEM_GEMM = 158912;
    const int SMEM_KNN  = 62464;
    cudaFuncSetAttribute(gemm_mma<128, 0>, cudaFuncAttributeMaxDynamicSharedMemorySize, SMEM_GEMM);
    cudaFuncSetAttribute(gemm_mma<KP3, 0>, cudaFuncAttributeMaxDynamicSharedMemorySize, SMEM_GEMM);
    cudaFuncSetAttribute(gemm_mma<KP3, 2>, cudaFuncAttributeMaxDynamicSharedMemorySize, SMEM_GEMM);
    cudaFuncSetAttribute(knn_mma, cudaFuncAttributeMaxDynamicSharedMemorySize, SMEM_KNN);

    const int knn_blocks = BC * (PP / 256);   // 512

    // setup
    padzero_kernel<<<NPTS / 256, 256>>>(xah, xal, yah, yal);
    wconv_kernel<<<(NP2 * KP3 + 255) / 256, 256>>>(mW1, 128, wh + 0 * NP2 * KP3, wl + 0 * NP2 * KP3);
    wconv_kernel<<<(NP2 * KP3 + 255) / 256, 256>>>(mW2, 264, wh + 1 * NP2 * KP3, wl + 1 * NP2 * KP3);
    wconv_kernel<<<(NP2 * KP3 + 255) / 256, 256>>>(mW3, 264, wh + 2 * NP2 * KP3, wl + 2 * NP2 * KP3);

    // conv1: d=1 -> c=32 (cols 0..31)
    knn1_kernel<<<knn_blocks, 256>>>(x, knn);
    edge_conv1_kernel<<<NPTS / 8, 256>>>(x, knn, c1W1, c1b1, c1W2, c1b2, f, fah, fal);
    // conv2: kNN on x1 via fused HMMA Gram (k-blocks 0..1), then edge conv (cols 32..63)
    sqnorm_kernel<<<NPTS / 256, 256>>>(fah, fal, 0, sq);
    knn_mma<<<BC * 16, 256, SMEM_KNN>>>(fah, fal, 0, sq, knn);
    edge_conv32<32, 1, true><<<NPTS / 128, 128>>>(f, 64, knn, c2W1, c2b1, c2W2, c2b2,
                                                  f + 32, 64, 32, fah, fal);
    // conv3: kNN on x2 (k-blocks 2..3), then edge conv (cols 64..127)
    sqnorm_kernel<<<NPTS / 256, 256>>>(fah, fal, 2, sq);
    knn_mma<<<BC * 16, 256, SMEM_KNN>>>(fah, fal, 2, sq, knn);
    edge_conv32<64, 2, false><<<2 * NPTS / 128, 128>>>(f + 32, 64, knn, c3W1, c3b1, c3W2, c3b2,
                                                       nullptr, 0, 64, fah, fal);

    // final MLP via double-buffered HMMA GEMMs (GEMM3 fuses final layer)
    dim3 gg(NPTS / 128);
    gemm_mma<128, 0><<<gg, 512, SMEM_GEMM>>>(fah, fal, wh + 0 * NP2 * KP3, wl + 0 * NP2 * KP3,
                                             mb1, xah, xal, nullptr, nullptr, nullptr);
    gemm_mma<KP3, 0><<<gg, 512, SMEM_GEMM>>>(xah, xal, wh + 1 * NP2 * KP3, wl + 1 * NP2 * KP3,
                                             mb2, yah, yal, nullptr, nullptr, nullptr);
    gemm_mma<KP3, 2><<<gg, 512, SMEM_GEMM>>>(yah, yal, wh + 2 * NP2 * KP3, wl + 2 * NP2 * KP3,
                                             mb3, nullptr, nullptr, mW4, mb4, out);
}